// round 12
// baseline (speedup 1.0000x reference)
#include <cuda_runtime.h>
#include <cuda_fp16.h>
#include <math.h>

#define NN 10000
#define NE 200000
#define NT 400000
#define NORB 9
#define HD 128
#define CFD 64
#define CD 32
#define R_TOT (NE * NORB)   // 1,800,000 flattened (edge,orb) rows

typedef unsigned long long u64;
typedef unsigned int u32;

// ---------------- scratch (device globals; no allocation allowed) ----------
__device__ float g_h[NN * 64];                     // [0:32)=silu(xh), [32:64)=sigm(xk)
__device__ __half g_cji_c[(size_t)NE * NORB * CD]; // 115.2 MB (fp16)
__device__ __half g_ckj_n[(size_t)NE * NORB * CD]; // 115.2 MB (fp16, pre-normalized)
__device__ float g_rbw[NE * NORB];
__device__ float g_agg[(size_t)NE * CD];
__device__ float g_nf[(size_t)NE * CD];            // node-feature MLP output
__device__ float g_acc[NN * CD];

// ---- activations (proven __expf path) ---------------------------------------
__device__ __forceinline__ float sigm(float x) { return 1.f / (1.f + __expf(-x)); }
__device__ __forceinline__ float silu(float x) { return x * sigm(x); }

__device__ __forceinline__ float warp_sum(float s) {
#pragma unroll
    for (int off = 16; off; off >>= 1) s += __shfl_xor_sync(0xffffffffu, s, off);
    return s;
}

// ---- packed fp32x2 FFMA2 (k5b W4 gemm) -------------------------------------
__device__ __forceinline__ void fma2(u64& d, u64 a, u64 b) {
    asm("fma.rn.f32x2 %0,%1,%2,%0;" : "+l"(d) : "l"(a), "l"(b));
}
__device__ __forceinline__ float unp_sum(u64 v) {
    float x, y; asm("mov.b64 {%0,%1},%2;" : "=f"(x), "=f"(y) : "l"(v)); return x + y;
}

// ---- tf32 helpers -----------------------------------------------------------
__device__ __forceinline__ u32 to_tf32(float f) {
    u32 r; asm("cvt.rna.tf32.f32 %0,%1;" : "=r"(r) : "f"(f)); return r;
}
__device__ __forceinline__ void mma_tf32(float& c0, float& c1, float& c2, float& c3,
                                         u32 a0, u32 a1, u32 a2, u32 a3,
                                         u32 b0, u32 b1) {
    asm("mma.sync.aligned.m16n8k8.row.col.f32.tf32.tf32.f32 "
        "{%0,%1,%2,%3},{%4,%5,%6,%7},{%8,%9},{%0,%1,%2,%3};"
        : "+f"(c0), "+f"(c1), "+f"(c2), "+f"(c3)
        : "r"(a0), "r"(a1), "r"(a2), "r"(a3), "r"(b0), "r"(b1));
}

// ---------------- K0: zero accumulators + rb_w = rb * cutoff_w -------------
__global__ void k0_init(const float* __restrict__ rb, const float* __restrict__ cw) {
    int i = blockIdx.x * blockDim.x + threadIdx.x;
    if (i < NE * CD) g_agg[i] = 0.f;
    if (i < NN * CD) g_acc[i] = 0.f;
    if (i < NE * NORB) g_rbw[i] = rb[i] * cw[i / NORB];
}

// ---------------- K1: h = x @ W1^T + b1; store silu(xh) / sigm(xk) ----------
__global__ void __launch_bounds__(256) k1_node(const float* __restrict__ x,
                                               const float* __restrict__ W1,
                                               const float* __restrict__ b1) {
    __shared__ float sW[HD * 64];
    __shared__ float sx[4][HD];
    int tid = threadIdx.x;
    for (int idx = tid; idx < 64 * HD; idx += 256) {
        int o = idx / HD, k = idx % HD;
        sW[k * 64 + o] = W1[idx];
    }
    int n0 = blockIdx.x * 4;
#pragma unroll
    for (int r = 0; r < 4; r++) {
        int n = n0 + r;
        if (n < NN)
            for (int k = tid; k < HD; k += 256) sx[r][k] = x[n * HD + k];
    }
    __syncthreads();
    int r = tid / 64, o = tid % 64;
    int n = n0 + r;
    if (n >= NN) return;
    float acc = b1[o];
#pragma unroll 8
    for (int k = 0; k < HD; k++) acc = fmaf(sx[r][k], sW[k * 64 + o], acc);
    g_h[n * 64 + o] = (o < 32) ? silu(acc) : sigm(acc);
}

// ---------------- K2: edge coeff MLP, tf32 tensor cores, A2 aliased on A1 ----
__global__ void __launch_bounds__(256) k2_mma(const float* __restrict__ cji,
                                              const float* __restrict__ W2,
                                              const float* __restrict__ W3) {
    __shared__ u32 sW2[32 * 68];       // [n][k] pad 68 (tf32 bits)
    __shared__ u32 sW3[64 * 36];       // [n][k] pad 36
    __shared__ u32 sA1[8][16 * 68];    // per-warp tile; A2 overlays same buffer
    int tid = threadIdx.x;
    for (int idx = tid; idx < 32 * 64; idx += 256) {
        int n = idx >> 6, k = idx & 63;
        sW2[n * 68 + k] = to_tf32(W2[idx]);
    }
    for (int idx = tid; idx < 64 * 32; idx += 256) {
        int n = idx >> 5, k = idx & 31;
        sW3[n * 36 + k] = to_tf32(W3[idx]);
    }
    __syncthreads();

    int w = tid >> 5, lane = tid & 31;
    int gq = lane >> 2, tq = lane & 3;
    long row0 = (long)blockIdx.x * 128 + w * 16;
    u32* A1 = sA1[w];
    u32* A2 = sA1[w];   // alias: A1 fully consumed into regs before A2 writes

    for (int i = lane; i < 256; i += 32) {
        int rl = i >> 4, c4 = i & 15;
        long rg = row0 + rl;
        uint4 v = make_uint4(0u, 0u, 0u, 0u);
        if (rg < R_TOT) {
            float4 f = *(const float4*)(cji + rg * 64 + c4 * 4);
            v.x = to_tf32(silu(f.x)); v.y = to_tf32(silu(f.y));
            v.z = to_tf32(silu(f.z)); v.w = to_tf32(silu(f.w));
        }
        *(uint4*)&A1[rl * 68 + c4 * 4] = v;
    }
    __syncwarp();

    float c1[4][4];
#pragma unroll
    for (int nt = 0; nt < 4; nt++)
#pragma unroll
        for (int j = 0; j < 4; j++) c1[nt][j] = 0.f;
#pragma unroll
    for (int k0 = 0; k0 < 64; k0 += 8) {
        u32 a0 = A1[gq * 68 + k0 + tq];
        u32 a1 = A1[(gq + 8) * 68 + k0 + tq];
        u32 a2 = A1[gq * 68 + k0 + tq + 4];
        u32 a3 = A1[(gq + 8) * 68 + k0 + tq + 4];
#pragma unroll
        for (int nt = 0; nt < 4; nt++) {
            u32 b0 = sW2[(nt * 8 + gq) * 68 + k0 + tq];
            u32 b1 = sW2[(nt * 8 + gq) * 68 + k0 + tq + 4];
            mma_tf32(c1[nt][0], c1[nt][1], c1[nt][2], c1[nt][3], a0, a1, a2, a3, b0, b1);
        }
    }
    __syncwarp();
#pragma unroll
    for (int nt = 0; nt < 4; nt++) {
        A2[gq * 36 + nt * 8 + 2 * tq]           = to_tf32(silu(c1[nt][0]));
        A2[gq * 36 + nt * 8 + 2 * tq + 1]       = to_tf32(silu(c1[nt][1]));
        A2[(gq + 8) * 36 + nt * 8 + 2 * tq]     = to_tf32(silu(c1[nt][2]));
        A2[(gq + 8) * 36 + nt * 8 + 2 * tq + 1] = to_tf32(silu(c1[nt][3]));
    }
    __syncwarp();

    float c2[8][4];
#pragma unroll
    for (int nt = 0; nt < 8; nt++)
#pragma unroll
        for (int j = 0; j < 4; j++) c2[nt][j] = 0.f;
#pragma unroll
    for (int k0 = 0; k0 < 32; k0 += 8) {
        u32 a0 = A2[gq * 36 + k0 + tq];
        u32 a1 = A2[(gq + 8) * 36 + k0 + tq];
        u32 a2 = A2[gq * 36 + k0 + tq + 4];
        u32 a3 = A2[(gq + 8) * 36 + k0 + tq + 4];
#pragma unroll
        for (int nt = 0; nt < 8; nt++) {
            u32 b0 = sW3[(nt * 8 + gq) * 36 + k0 + tq];
            u32 b1 = sW3[(nt * 8 + gq) * 36 + k0 + tq + 4];
            mma_tf32(c2[nt][0], c2[nt][1], c2[nt][2], c2[nt][3], a0, a1, a2, a3, b0, b1);
        }
    }

    long rA = row0 + gq, rB = row0 + gq + 8;
    if (rA < R_TOT) {
#pragma unroll
        for (int nt = 0; nt < 4; nt++)
            *(__half2*)&g_cji_c[rA * 32 + nt * 8 + 2 * tq] = __floats2half2_rn(c2[nt][0], c2[nt][1]);
    }
    if (rB < R_TOT) {
#pragma unroll
        for (int nt = 0; nt < 4; nt++)
            *(__half2*)&g_cji_c[rB * 32 + nt * 8 + 2 * tq] = __floats2half2_rn(c2[nt][2], c2[nt][3]);
    }
    float sa = 0.f, sb = 0.f;
#pragma unroll
    for (int nt = 4; nt < 8; nt++) {
        sa = fmaf(c2[nt][0], c2[nt][0], fmaf(c2[nt][1], c2[nt][1], sa));
        sb = fmaf(c2[nt][2], c2[nt][2], fmaf(c2[nt][3], c2[nt][3], sb));
    }
    sa += __shfl_xor_sync(0xffffffffu, sa, 1);
    sa += __shfl_xor_sync(0xffffffffu, sa, 2);
    sb += __shfl_xor_sync(0xffffffffu, sb, 1);
    sb += __shfl_xor_sync(0xffffffffu, sb, 2);
    float ia = 1.f / fmaxf(sqrtf(sa), 1e-12f);
    float ib = 1.f / fmaxf(sqrtf(sb), 1e-12f);
    if (rA < R_TOT) {
#pragma unroll
        for (int nt = 4; nt < 8; nt++)
            *(__half2*)&g_ckj_n[rA * 32 + (nt - 4) * 8 + 2 * tq] =
                __floats2half2_rn(c2[nt][0] * ia, c2[nt][1] * ia);
    }
    if (rB < R_TOT) {
#pragma unroll
        for (int nt = 4; nt < 8; nt++)
            *(__half2*)&g_ckj_n[rB * 32 + (nt - 4) * 8 + 2 * tq] =
                __floats2half2_rn(c2[nt][2] * ib, c2[nt][3] * ib);
    }
}

// ---------------- K5a: nf MLP on tensor cores, A2 aliased on A1 --------------
__global__ void __launch_bounds__(256) k5a_nf(const float* __restrict__ W5,
                                              const float* __restrict__ b5,
                                              const float* __restrict__ W6,
                                              const float* __restrict__ b6,
                                              const int* __restrict__ idx_i,
                                              const int* __restrict__ idx_j) {
    __shared__ u32 sW5[32 * 68];
    __shared__ u32 sW6[32 * 36];
    __shared__ float sb5[32], sb6[32];
    __shared__ u32 sA1[8][16 * 68];   // A2 overlays
    int tid = threadIdx.x;
    for (int idx = tid; idx < 32 * 64; idx += 256) {
        int n = idx >> 6, k = idx & 63;
        sW5[n * 68 + k] = to_tf32(W5[idx]);
    }
    for (int idx = tid; idx < 32 * 32; idx += 256) {
        int n = idx >> 5, k = idx & 31;
        sW6[n * 36 + k] = to_tf32(W6[idx]);
    }
    if (tid < 32) { sb5[tid] = b5[tid]; sb6[tid] = b6[tid]; }
    __syncthreads();

    int w = tid >> 5, lane = tid & 31;
    int gq = lane >> 2, tq = lane & 3;
    long row0 = (long)blockIdx.x * 128 + w * 16;
    u32* A1 = sA1[w];
    u32* A2 = sA1[w];

    for (int i = lane; i < 256; i += 32) {
        int rl = i >> 4, c4 = i & 15;
        long e = row0 + rl;
        uint4 v = make_uint4(0u, 0u, 0u, 0u);
        if (e < NE) {
            int n = (c4 < 8) ? __ldg(&idx_i[e]) : __ldg(&idx_j[e]);
            float4 f = *(const float4*)&g_h[n * 64 + (c4 & 7) * 4];
            v.x = to_tf32(f.x); v.y = to_tf32(f.y);
            v.z = to_tf32(f.z); v.w = to_tf32(f.w);
        }
        *(uint4*)&A1[rl * 68 + c4 * 4] = v;
    }
    __syncwarp();

    float c1[4][4];
#pragma unroll
    for (int nt = 0; nt < 4; nt++)
#pragma unroll
        for (int j = 0; j < 4; j++) c1[nt][j] = 0.f;
#pragma unroll
    for (int k0 = 0; k0 < 64; k0 += 8) {
        u32 a0 = A1[gq * 68 + k0 + tq];
        u32 a1 = A1[(gq + 8) * 68 + k0 + tq];
        u32 a2 = A1[gq * 68 + k0 + tq + 4];
        u32 a3 = A1[(gq + 8) * 68 + k0 + tq + 4];
#pragma unroll
        for (int nt = 0; nt < 4; nt++) {
            u32 b0 = sW5[(nt * 8 + gq) * 68 + k0 + tq];
            u32 b1 = sW5[(nt * 8 + gq) * 68 + k0 + tq + 4];
            mma_tf32(c1[nt][0], c1[nt][1], c1[nt][2], c1[nt][3], a0, a1, a2, a3, b0, b1);
        }
    }
    __syncwarp();
#pragma unroll
    for (int nt = 0; nt < 4; nt++) {
        int col = nt * 8 + 2 * tq;
        A2[gq * 36 + col]           = to_tf32(silu(c1[nt][0] + sb5[col]));
        A2[gq * 36 + col + 1]       = to_tf32(silu(c1[nt][1] + sb5[col + 1]));
        A2[(gq + 8) * 36 + col]     = to_tf32(silu(c1[nt][2] + sb5[col]));
        A2[(gq + 8) * 36 + col + 1] = to_tf32(silu(c1[nt][3] + sb5[col + 1]));
    }
    __syncwarp();

    float c2[4][4];
#pragma unroll
    for (int nt = 0; nt < 4; nt++)
#pragma unroll
        for (int j = 0; j < 4; j++) c2[nt][j] = 0.f;
#pragma unroll
    for (int k0 = 0; k0 < 32; k0 += 8) {
        u32 a0 = A2[gq * 36 + k0 + tq];
        u32 a1 = A2[(gq + 8) * 36 + k0 + tq];
        u32 a2 = A2[gq * 36 + k0 + tq + 4];
        u32 a3 = A2[(gq + 8) * 36 + k0 + tq + 4];
#pragma unroll
        for (int nt = 0; nt < 4; nt++) {
            u32 b0 = sW6[(nt * 8 + gq) * 36 + k0 + tq];
            u32 b1 = sW6[(nt * 8 + gq) * 36 + k0 + tq + 4];
            mma_tf32(c2[nt][0], c2[nt][1], c2[nt][2], c2[nt][3], a0, a1, a2, a3, b0, b1);
        }
    }
    long rA = row0 + gq, rB = row0 + gq + 8;
    if (rA < NE) {
#pragma unroll
        for (int nt = 0; nt < 4; nt++) {
            int col = nt * 8 + 2 * tq;
            *(float2*)&g_nf[rA * 32 + col] =
                make_float2(c2[nt][0] + sb6[col], c2[nt][1] + sb6[col + 1]);
        }
    }
    if (rB < NE) {
#pragma unroll
        for (int nt = 0; nt < 4; nt++) {
            int col = nt * 8 + 2 * tq;
            *(float2*)&g_nf[rB * 32 + col] =
                make_float2(c2[nt][2] + sb6[col], c2[nt][3] + sb6[col + 1]);
        }
    }
}

// ---------------- K3: triplets -> edge aggregation, 4 triplets per warp ------
__global__ void __launch_bounds__(256) k3_tri(const float* __restrict__ shb,
                                              const int* __restrict__ e_kj,
                                              const int* __restrict__ e_ji,
                                              const int* __restrict__ t_k) {
    int w = threadIdx.x >> 5, lane = threadIdx.x & 31;
    int t0 = (blockIdx.x * 8 + w) * 4;
    if (t0 >= NT) return;
    int kj[4], ji[4], kn[4];
#pragma unroll
    for (int q = 0; q < 4; q++) {
        int t = t0 + q;
        kj[q] = e_kj[t]; ji[q] = e_ji[t]; kn[q] = t_k[t];
    }
    float acc[4] = {0.f, 0.f, 0.f, 0.f};
#pragma unroll
    for (int d = 0; d < NORB; d++) {
#pragma unroll
        for (int q = 0; q < 4; q++) {
            float cf = __ldg(&g_rbw[kj[q] * NORB + d]) * __ldg(&shb[(t0 + q) * NORB + d]);
            float ck = __half2float(__ldg(&g_ckj_n[((size_t)kj[q] * NORB + d) * CD + lane]));
            acc[q] = fmaf(cf, ck, acc[q]);
        }
    }
    float s[4];
#pragma unroll
    for (int q = 0; q < 4; q++) s[q] = acc[q] * acc[q];
#pragma unroll
    for (int off = 16; off; off >>= 1) {
#pragma unroll
        for (int q = 0; q < 4; q++)
            s[q] += __shfl_xor_sync(0xffffffffu, s[q], off);
    }
#pragma unroll
    for (int q = 0; q < 4; q++) {
        float tw = acc[q] * (1.f / fmaxf(sqrtf(s[q]), 1e-12f)) * g_h[kn[q] * 64 + 32 + lane];
        atomicAdd(&g_agg[(size_t)ji[q] * CD + lane], tw);
    }
}

// ---------------- K5b: tbw + lcao + scatter, 2 edges per warp ----------------
__global__ void __launch_bounds__(256) k5b_edge(const float* __restrict__ W4,
                                                const float* __restrict__ b4,
                                                const int* __restrict__ idx_i) {
    __shared__ __align__(16) float sW4[32 * 36];
    __shared__ __align__(16) float sag[8][2][32];
    int tid = threadIdx.x;
    for (int idx = tid; idx < 32 * 32; idx += 256) {
        int c = idx / 32, k = idx % 32;
        sW4[c * 36 + k] = W4[idx];
    }
    __syncthreads();
    int w = tid >> 5, lane = tid & 31;
    int e0 = (blockIdx.x * 8 + w) * 2;
    if (e0 >= NE) return;
    int e1 = e0 + 1;

    // hoisted independent gathers for both edges (overlap the W4 GEMM)
    float vv0[NORB], vv1[NORB];
    size_t base0 = (size_t)e0 * (NORB * CD);
    size_t base1 = (size_t)e1 * (NORB * CD);
#pragma unroll
    for (int d = 0; d < NORB; d++) {
        vv0[d] = __half2float(__ldg(&g_cji_c[base0 + d * 32 + lane]));
        vv1[d] = __half2float(__ldg(&g_cji_c[base1 + d * 32 + lane]));
    }
    float nf0 = __ldg(&g_nf[(size_t)e0 * CD + lane]);
    float nf1 = __ldg(&g_nf[(size_t)e1 * CD + lane]);
    float rw0[NORB], rw1[NORB];
#pragma unroll
    for (int d = 0; d < NORB; d++) {
        rw0[d] = __ldg(&g_rbw[e0 * NORB + d]);
        rw1[d] = __ldg(&g_rbw[e1 * NORB + d]);
    }

    // tbw = silu(agg) @ W4^T + b4, both edges
    sag[w][0][lane] = silu(g_agg[(size_t)e0 * CD + lane]);
    sag[w][1][lane] = silu(g_agg[(size_t)e1 * CD + lane]);
    __syncwarp();
    u64 t20 = 0ull, t21 = 0ull;
#pragma unroll
    for (int k4 = 0; k4 < 8; k4++) {
        ulonglong2 wv = *(const ulonglong2*)&sW4[lane * 36 + k4 * 4];
        ulonglong2 a0 = *(const ulonglong2*)&sag[w][0][k4 * 4];
        ulonglong2 a1 = *(const ulonglong2*)&sag[w][1][k4 * 4];
        fma2(t20, a0.x, wv.x); fma2(t20, a0.y, wv.y);
        fma2(t21, a1.x, wv.x); fma2(t21, a1.y, wv.y);
    }
    float bb = b4[lane];
    float tb0 = 1.f + bb + unp_sum(t20);
    float tb1 = 1.f + bb + unp_sum(t21);

    // batched per-orbital norms for both edges: 18 values, one butterfly cascade
    float ss0[NORB], ss1[NORB];
#pragma unroll
    for (int d = 0; d < NORB; d++) {
        float x0 = vv0[d] * tb0, x1 = vv1[d] * tb1;
        ss0[d] = x0 * x0; ss1[d] = x1 * x1;
    }
#pragma unroll
    for (int off = 16; off; off >>= 1) {
#pragma unroll
        for (int d = 0; d < NORB; d++) {
            ss0[d] += __shfl_xor_sync(0xffffffffu, ss0[d], off);
            ss1[d] += __shfl_xor_sync(0xffffffffu, ss1[d], off);
        }
    }
    float lc0 = 0.f, lc1 = 0.f;
#pragma unroll
    for (int d = 0; d < NORB; d++) {
        lc0 = fmaf(rw0[d] * (1.f / fmaxf(sqrtf(ss0[d]), 1e-12f)), vv0[d], lc0);
        lc1 = fmaf(rw1[d] * (1.f / fmaxf(sqrtf(ss1[d]), 1e-12f)), vv1[d], lc1);
    }
    lc0 *= tb0; lc1 *= tb1;
    float s0 = lc0 * lc0, s1 = lc1 * lc1;
#pragma unroll
    for (int off = 16; off; off >>= 1) {
        s0 += __shfl_xor_sync(0xffffffffu, s0, off);
        s1 += __shfl_xor_sync(0xffffffffu, s1, off);
    }
    lc0 *= 1.f / fmaxf(sqrtf(s0), 1e-12f);
    lc1 *= 1.f / fmaxf(sqrtf(s1), 1e-12f);

    int ni0 = idx_i[e0], ni1 = idx_i[e1];
    atomicAdd(&g_acc[ni0 * CD + lane], lc0 * nf0);
    atomicAdd(&g_acc[ni1 * CD + lane], lc1 * nf1);
}

// ---------------- K6: out = x + acc @ W7^T ----------------------------------
__global__ void __launch_bounds__(256) k6_out(const float* __restrict__ x,
                                              const float* __restrict__ W7,
                                              float* __restrict__ out) {
    __shared__ float sW[32 * 128];
    __shared__ float sa[2][32];
    int tid = threadIdx.x;
    for (int idx = tid; idx < 128 * 32; idx += 256) {
        int hc = idx / 32, c = idx % 32;
        sW[c * 128 + hc] = W7[idx];
    }
    int n0 = blockIdx.x * 2;
    if (tid < 64) {
        int r = tid >> 5, c = tid & 31;
        int n = n0 + r;
        if (n < NN) sa[r][c] = g_acc[n * 32 + c];
    }
    __syncthreads();
    int r = tid >> 7, hc = tid & 127;
    int n = n0 + r;
    if (n >= NN) return;
    float acc = x[n * 128 + hc];
#pragma unroll
    for (int c = 0; c < 32; c++) acc = fmaf(sa[r][c], sW[c * 128 + hc], acc);
    out[n * 128 + hc] = acc;
}

// ---------------- host launcher ---------------------------------------------
extern "C" void kernel_launch(void* const* d_in, const int* in_sizes, int n_in,
                              void* d_out, int out_size) {
    int o_ii, o_ij, o_tk, o_ekj, o_eji;
    int o_W1, o_b1, o_W2, o_W3, o_W4, o_b4, o_W5, o_b5, o_W6, o_b6, o_W7;
    if (in_sizes[5] == NE) { // dict order: idx_i at slot 5
        o_ii = 5; o_ij = 6; o_tk = 7; o_ekj = 8; o_eji = 9;
        o_W1 = 10; o_b1 = 11; o_W2 = 12; o_W3 = 13; o_W4 = 14; o_b4 = 15;
        o_W5 = 16; o_b5 = 17; o_W6 = 18; o_b6 = 19; o_W7 = 20;
    } else {                 // signature order: W1 at slot 5
        o_W1 = 5; o_b1 = 6; o_W2 = 7; o_W3 = 8; o_W4 = 9; o_b4 = 10;
        o_W5 = 11; o_b5 = 12; o_W6 = 13; o_b6 = 14; o_W7 = 15;
        o_ii = 16; o_ij = 17; o_tk = 18; o_ekj = 19; o_eji = 20;
    }
    const float* x   = (const float*)d_in[0];
    const float* cji = (const float*)d_in[1];
    const float* cw  = (const float*)d_in[2];
    const float* rb  = (const float*)d_in[3];
    const float* shb = (const float*)d_in[4];
    const int* ii  = (const int*)d_in[o_ii];
    const int* ij  = (const int*)d_in[o_ij];
    const int* tk  = (const int*)d_in[o_tk];
    const int* ekj = (const int*)d_in[o_ekj];
    const int* eji = (const int*)d_in[o_eji];
    const float* W1 = (const float*)d_in[o_W1];
    const float* b1 = (const float*)d_in[o_b1];
    const float* W2 = (const float*)d_in[o_W2];
    const float* W3 = (const float*)d_in[o_W3];
    const float* W4 = (const float*)d_in[o_W4];
    const float* b4 = (const float*)d_in[o_b4];
    const float* W5 = (const float*)d_in[o_W5];
    const float* b5 = (const float*)d_in[o_b5];
    const float* W6 = (const float*)d_in[o_W6];
    const float* b6 = (const float*)d_in[o_b6];
    const float* W7 = (const float*)d_in[o_W7];
    float* out = (float*)d_out;

    k0_init<<<(NE * CD + 255) / 256, 256>>>(rb, cw);
    k1_node<<<(NN + 3) / 4, 256>>>(x, W1, b1);
    k2_mma<<<(R_TOT + 127) / 128, 256>>>(cji, W2, W3);
    k5a_nf<<<(NE + 127) / 128, 256>>>(W5, b5, W6, b6, ii, ij);
    k3_tri<<<(NT + 31) / 32, 256>>>(shb, ekj, eji, tk);
    k5b_edge<<<(NE + 15) / 16, 256>>>(W4, b4, ii);
    k6_out<<<(NN + 1) / 2, 256>>>(x, W7, out);
}

// round 13
// speedup vs baseline: 1.1792x; 1.1792x over previous
#include <cuda_runtime.h>
#include <cuda_fp16.h>
#include <math.h>

#define NN 10000
#define NE 200000
#define NT 400000
#define NORB 9
#define HD 128
#define CFD 64
#define CD 32
#define R_TOT (NE * NORB)   // 1,800,000 flattened (edge,orb) rows
#define K2_BLOCKS 592       // 148 SMs x 4 resident CTAs (smem/reg-limited)

typedef unsigned long long u64;
typedef unsigned int u32;

// ---------------- scratch (device globals; no allocation allowed) ----------
__device__ float g_h[NN * 64];                     // [0:32)=silu(xh), [32:64)=sigm(xk)
__device__ __half g_cji_c[(size_t)NE * NORB * CD]; // 115.2 MB (fp16)
__device__ __half g_ckj_n[(size_t)NE * NORB * CD]; // 115.2 MB (fp16, pre-normalized)
__device__ float g_rbw[NE * NORB];
__device__ float g_agg[(size_t)NE * CD];
__device__ float g_nf[(size_t)NE * CD];            // node-feature MLP output
__device__ float g_acc[NN * CD];

// ---- activations (proven __expf path) ---------------------------------------
__device__ __forceinline__ float sigm(float x) { return 1.f / (1.f + __expf(-x)); }
__device__ __forceinline__ float silu(float x) { return x * sigm(x); }

__device__ __forceinline__ float warp_sum(float s) {
#pragma unroll
    for (int off = 16; off; off >>= 1) s += __shfl_xor_sync(0xffffffffu, s, off);
    return s;
}

// ---- packed fp32x2 FFMA2 (k5b W4 gemm) -------------------------------------
__device__ __forceinline__ void fma2(u64& d, u64 a, u64 b) {
    asm("fma.rn.f32x2 %0,%1,%2,%0;" : "+l"(d) : "l"(a), "l"(b));
}
__device__ __forceinline__ float unp_sum(u64 v) {
    float x, y; asm("mov.b64 {%0,%1},%2;" : "=f"(x), "=f"(y) : "l"(v)); return x + y;
}

// ---- tf32 helpers -----------------------------------------------------------
__device__ __forceinline__ u32 to_tf32(float f) {
    u32 r; asm("cvt.rna.tf32.f32 %0,%1;" : "=r"(r) : "f"(f)); return r;
}
__device__ __forceinline__ void mma_tf32(float& c0, float& c1, float& c2, float& c3,
                                         u32 a0, u32 a1, u32 a2, u32 a3,
                                         u32 b0, u32 b1) {
    asm("mma.sync.aligned.m16n8k8.row.col.f32.tf32.tf32.f32 "
        "{%0,%1,%2,%3},{%4,%5,%6,%7},{%8,%9},{%0,%1,%2,%3};"
        : "+f"(c0), "+f"(c1), "+f"(c2), "+f"(c3)
        : "r"(a0), "r"(a1), "r"(a2), "r"(a3), "r"(b0), "r"(b1));
}

// ---------------- K0: zero accumulators + rb_w = rb * cutoff_w -------------
__global__ void k0_init(const float* __restrict__ rb, const float* __restrict__ cw) {
    int i = blockIdx.x * blockDim.x + threadIdx.x;
    if (i < NE * CD) g_agg[i] = 0.f;
    if (i < NN * CD) g_acc[i] = 0.f;
    if (i < NE * NORB) g_rbw[i] = rb[i] * cw[i / NORB];
}

// ---------------- K1: h = x @ W1^T + b1; store silu(xh) / sigm(xk) ----------
__global__ void __launch_bounds__(256) k1_node(const float* __restrict__ x,
                                               const float* __restrict__ W1,
                                               const float* __restrict__ b1) {
    __shared__ float sW[HD * 64];
    __shared__ float sx[4][HD];
    int tid = threadIdx.x;
    for (int idx = tid; idx < 64 * HD; idx += 256) {
        int o = idx / HD, k = idx % HD;
        sW[k * 64 + o] = W1[idx];
    }
    int n0 = blockIdx.x * 4;
#pragma unroll
    for (int r = 0; r < 4; r++) {
        int n = n0 + r;
        if (n < NN)
            for (int k = tid; k < HD; k += 256) sx[r][k] = x[n * HD + k];
    }
    __syncthreads();
    int r = tid / 64, o = tid % 64;
    int n = n0 + r;
    if (n >= NN) return;
    float acc = b1[o];
#pragma unroll 8
    for (int k = 0; k < HD; k++) acc = fmaf(sx[r][k], sW[k * 64 + o], acc);
    g_h[n * 64 + o] = (o < 32) ? silu(acc) : sigm(acc);
}

// ---------------- K2: edge coeff MLP, tf32 MMA, PERSISTENT grid-stride -------
__global__ void __launch_bounds__(256) k2_mma(const float* __restrict__ cji,
                                              const float* __restrict__ W2,
                                              const float* __restrict__ W3) {
    __shared__ u32 sW2[32 * 68];       // [n][k] pad 68 (tf32 bits)
    __shared__ u32 sW3[64 * 36];       // [n][k] pad 36
    __shared__ u32 sA1[8][16 * 68];    // per-warp tile; A2 overlays same buffer
    int tid = threadIdx.x;
    for (int idx = tid; idx < 32 * 64; idx += 256) {
        int n = idx >> 6, k = idx & 63;
        sW2[n * 68 + k] = to_tf32(W2[idx]);
    }
    for (int idx = tid; idx < 64 * 32; idx += 256) {
        int n = idx >> 5, k = idx & 31;
        sW3[n * 36 + k] = to_tf32(W3[idx]);
    }
    __syncthreads();

    int w = tid >> 5, lane = tid & 31;
    int gq = lane >> 2, tq = lane & 3;
    u32* A1 = sA1[w];
    u32* A2 = sA1[w];   // alias: A1 fully consumed into regs before A2 writes

    const int n_tiles = (R_TOT + 15) / 16;      // 112500
    const int gw0 = blockIdx.x * 8 + w;         // global warp id
    const int gw_stride = K2_BLOCKS * 8;        // 4736

    for (int tile = gw0; tile < n_tiles; tile += gw_stride) {
        long row0 = (long)tile * 16;

        // stage 16 rows of silu(cji) as tf32 (coalesced float4 per warp)
        for (int i = lane; i < 256; i += 32) {
            int rl = i >> 4, c4 = i & 15;
            long rg = row0 + rl;
            uint4 v = make_uint4(0u, 0u, 0u, 0u);
            if (rg < R_TOT) {
                float4 f = *(const float4*)(cji + rg * 64 + c4 * 4);
                v.x = to_tf32(silu(f.x)); v.y = to_tf32(silu(f.y));
                v.z = to_tf32(silu(f.z)); v.w = to_tf32(silu(f.w));
            }
            *(uint4*)&A1[rl * 68 + c4 * 4] = v;
        }
        __syncwarp();

        float c1[4][4];
#pragma unroll
        for (int nt = 0; nt < 4; nt++)
#pragma unroll
            for (int j = 0; j < 4; j++) c1[nt][j] = 0.f;
#pragma unroll
        for (int k0 = 0; k0 < 64; k0 += 8) {
            u32 a0 = A1[gq * 68 + k0 + tq];
            u32 a1 = A1[(gq + 8) * 68 + k0 + tq];
            u32 a2 = A1[gq * 68 + k0 + tq + 4];
            u32 a3 = A1[(gq + 8) * 68 + k0 + tq + 4];
#pragma unroll
            for (int nt = 0; nt < 4; nt++) {
                u32 b0 = sW2[(nt * 8 + gq) * 68 + k0 + tq];
                u32 b1 = sW2[(nt * 8 + gq) * 68 + k0 + tq + 4];
                mma_tf32(c1[nt][0], c1[nt][1], c1[nt][2], c1[nt][3], a0, a1, a2, a3, b0, b1);
            }
        }
        __syncwarp();
#pragma unroll
        for (int nt = 0; nt < 4; nt++) {
            A2[gq * 36 + nt * 8 + 2 * tq]           = to_tf32(silu(c1[nt][0]));
            A2[gq * 36 + nt * 8 + 2 * tq + 1]       = to_tf32(silu(c1[nt][1]));
            A2[(gq + 8) * 36 + nt * 8 + 2 * tq]     = to_tf32(silu(c1[nt][2]));
            A2[(gq + 8) * 36 + nt * 8 + 2 * tq + 1] = to_tf32(silu(c1[nt][3]));
        }
        __syncwarp();

        float c2[8][4];
#pragma unroll
        for (int nt = 0; nt < 8; nt++)
#pragma unroll
            for (int j = 0; j < 4; j++) c2[nt][j] = 0.f;
#pragma unroll
        for (int k0 = 0; k0 < 32; k0 += 8) {
            u32 a0 = A2[gq * 36 + k0 + tq];
            u32 a1 = A2[(gq + 8) * 36 + k0 + tq];
            u32 a2 = A2[gq * 36 + k0 + tq + 4];
            u32 a3 = A2[(gq + 8) * 36 + k0 + tq + 4];
#pragma unroll
            for (int nt = 0; nt < 8; nt++) {
                u32 b0 = sW3[(nt * 8 + gq) * 36 + k0 + tq];
                u32 b1 = sW3[(nt * 8 + gq) * 36 + k0 + tq + 4];
                mma_tf32(c2[nt][0], c2[nt][1], c2[nt][2], c2[nt][3], a0, a1, a2, a3, b0, b1);
            }
        }

        long rA = row0 + gq, rB = row0 + gq + 8;
        if (rA < R_TOT) {
#pragma unroll
            for (int nt = 0; nt < 4; nt++)
                *(__half2*)&g_cji_c[rA * 32 + nt * 8 + 2 * tq] = __floats2half2_rn(c2[nt][0], c2[nt][1]);
        }
        if (rB < R_TOT) {
#pragma unroll
            for (int nt = 0; nt < 4; nt++)
                *(__half2*)&g_cji_c[rB * 32 + nt * 8 + 2 * tq] = __floats2half2_rn(c2[nt][2], c2[nt][3]);
        }
        float sa = 0.f, sb = 0.f;
#pragma unroll
        for (int nt = 4; nt < 8; nt++) {
            sa = fmaf(c2[nt][0], c2[nt][0], fmaf(c2[nt][1], c2[nt][1], sa));
            sb = fmaf(c2[nt][2], c2[nt][2], fmaf(c2[nt][3], c2[nt][3], sb));
        }
        sa += __shfl_xor_sync(0xffffffffu, sa, 1);
        sa += __shfl_xor_sync(0xffffffffu, sa, 2);
        sb += __shfl_xor_sync(0xffffffffu, sb, 1);
        sb += __shfl_xor_sync(0xffffffffu, sb, 2);
        float ia = 1.f / fmaxf(sqrtf(sa), 1e-12f);
        float ib = 1.f / fmaxf(sqrtf(sb), 1e-12f);
        if (rA < R_TOT) {
#pragma unroll
            for (int nt = 4; nt < 8; nt++)
                *(__half2*)&g_ckj_n[rA * 32 + (nt - 4) * 8 + 2 * tq] =
                    __floats2half2_rn(c2[nt][0] * ia, c2[nt][1] * ia);
        }
        if (rB < R_TOT) {
#pragma unroll
            for (int nt = 4; nt < 8; nt++)
                *(__half2*)&g_ckj_n[rB * 32 + (nt - 4) * 8 + 2 * tq] =
                    __floats2half2_rn(c2[nt][2] * ib, c2[nt][3] * ib);
        }
        __syncwarp();   // protect A1 against next iteration's staging
    }
}

// ---------------- K5a: nf MLP on tensor cores, A2 aliased on A1 --------------
__global__ void __launch_bounds__(256) k5a_nf(const float* __restrict__ W5,
                                              const float* __restrict__ b5,
                                              const float* __restrict__ W6,
                                              const float* __restrict__ b6,
                                              const int* __restrict__ idx_i,
                                              const int* __restrict__ idx_j) {
    __shared__ u32 sW5[32 * 68];
    __shared__ u32 sW6[32 * 36];
    __shared__ float sb5[32], sb6[32];
    __shared__ u32 sA1[8][16 * 68];   // A2 overlays
    int tid = threadIdx.x;
    for (int idx = tid; idx < 32 * 64; idx += 256) {
        int n = idx >> 6, k = idx & 63;
        sW5[n * 68 + k] = to_tf32(W5[idx]);
    }
    for (int idx = tid; idx < 32 * 32; idx += 256) {
        int n = idx >> 5, k = idx & 31;
        sW6[n * 36 + k] = to_tf32(W6[idx]);
    }
    if (tid < 32) { sb5[tid] = b5[tid]; sb6[tid] = b6[tid]; }
    __syncthreads();

    int w = tid >> 5, lane = tid & 31;
    int gq = lane >> 2, tq = lane & 3;
    long row0 = (long)blockIdx.x * 128 + w * 16;
    u32* A1 = sA1[w];
    u32* A2 = sA1[w];

    for (int i = lane; i < 256; i += 32) {
        int rl = i >> 4, c4 = i & 15;
        long e = row0 + rl;
        uint4 v = make_uint4(0u, 0u, 0u, 0u);
        if (e < NE) {
            int n = (c4 < 8) ? __ldg(&idx_i[e]) : __ldg(&idx_j[e]);
            float4 f = *(const float4*)&g_h[n * 64 + (c4 & 7) * 4];
            v.x = to_tf32(f.x); v.y = to_tf32(f.y);
            v.z = to_tf32(f.z); v.w = to_tf32(f.w);
        }
        *(uint4*)&A1[rl * 68 + c4 * 4] = v;
    }
    __syncwarp();

    float c1[4][4];
#pragma unroll
    for (int nt = 0; nt < 4; nt++)
#pragma unroll
        for (int j = 0; j < 4; j++) c1[nt][j] = 0.f;
#pragma unroll
    for (int k0 = 0; k0 < 64; k0 += 8) {
        u32 a0 = A1[gq * 68 + k0 + tq];
        u32 a1 = A1[(gq + 8) * 68 + k0 + tq];
        u32 a2 = A1[gq * 68 + k0 + tq + 4];
        u32 a3 = A1[(gq + 8) * 68 + k0 + tq + 4];
#pragma unroll
        for (int nt = 0; nt < 4; nt++) {
            u32 b0 = sW5[(nt * 8 + gq) * 68 + k0 + tq];
            u32 b1 = sW5[(nt * 8 + gq) * 68 + k0 + tq + 4];
            mma_tf32(c1[nt][0], c1[nt][1], c1[nt][2], c1[nt][3], a0, a1, a2, a3, b0, b1);
        }
    }
    __syncwarp();
#pragma unroll
    for (int nt = 0; nt < 4; nt++) {
        int col = nt * 8 + 2 * tq;
        A2[gq * 36 + col]           = to_tf32(silu(c1[nt][0] + sb5[col]));
        A2[gq * 36 + col + 1]       = to_tf32(silu(c1[nt][1] + sb5[col + 1]));
        A2[(gq + 8) * 36 + col]     = to_tf32(silu(c1[nt][2] + sb5[col]));
        A2[(gq + 8) * 36 + col + 1] = to_tf32(silu(c1[nt][3] + sb5[col + 1]));
    }
    __syncwarp();

    float c2[4][4];
#pragma unroll
    for (int nt = 0; nt < 4; nt++)
#pragma unroll
        for (int j = 0; j < 4; j++) c2[nt][j] = 0.f;
#pragma unroll
    for (int k0 = 0; k0 < 32; k0 += 8) {
        u32 a0 = A2[gq * 36 + k0 + tq];
        u32 a1 = A2[(gq + 8) * 36 + k0 + tq];
        u32 a2 = A2[gq * 36 + k0 + tq + 4];
        u32 a3 = A2[(gq + 8) * 36 + k0 + tq + 4];
#pragma unroll
        for (int nt = 0; nt < 4; nt++) {
            u32 b0 = sW6[(nt * 8 + gq) * 36 + k0 + tq];
            u32 b1 = sW6[(nt * 8 + gq) * 36 + k0 + tq + 4];
            mma_tf32(c2[nt][0], c2[nt][1], c2[nt][2], c2[nt][3], a0, a1, a2, a3, b0, b1);
        }
    }
    long rA = row0 + gq, rB = row0 + gq + 8;
    if (rA < NE) {
#pragma unroll
        for (int nt = 0; nt < 4; nt++) {
            int col = nt * 8 + 2 * tq;
            *(float2*)&g_nf[rA * 32 + col] =
                make_float2(c2[nt][0] + sb6[col], c2[nt][1] + sb6[col + 1]);
        }
    }
    if (rB < NE) {
#pragma unroll
        for (int nt = 0; nt < 4; nt++) {
            int col = nt * 8 + 2 * tq;
            *(float2*)&g_nf[rB * 32 + col] =
                make_float2(c2[nt][2] + sb6[col], c2[nt][3] + sb6[col + 1]);
        }
    }
}

// ---------------- K3: triplets -> edge aggregation, 2 triplets per warp ------
__global__ void __launch_bounds__(256) k3_tri(const float* __restrict__ shb,
                                              const int* __restrict__ e_kj,
                                              const int* __restrict__ e_ji,
                                              const int* __restrict__ t_k) {
    int w = threadIdx.x >> 5, lane = threadIdx.x & 31;
    int t0 = (blockIdx.x * 8 + w) * 2;
    if (t0 >= NT) return;
    int t1 = t0 + 1;
    int kj0 = e_kj[t0], ji0 = e_ji[t0], kn0 = t_k[t0];
    int kj1 = e_kj[t1], ji1 = e_ji[t1], kn1 = t_k[t1];
    float acc0 = 0.f, acc1 = 0.f;
#pragma unroll
    for (int d = 0; d < NORB; d++) {
        float cf0 = __ldg(&g_rbw[kj0 * NORB + d]) * __ldg(&shb[t0 * NORB + d]);
        float cf1 = __ldg(&g_rbw[kj1 * NORB + d]) * __ldg(&shb[t1 * NORB + d]);
        float ck0 = __half2float(__ldg(&g_ckj_n[((size_t)kj0 * NORB + d) * CD + lane]));
        float ck1 = __half2float(__ldg(&g_ckj_n[((size_t)kj1 * NORB + d) * CD + lane]));
        acc0 = fmaf(cf0, ck0, acc0);
        acc1 = fmaf(cf1, ck1, acc1);
    }
    float s0 = acc0 * acc0, s1 = acc1 * acc1;
#pragma unroll
    for (int off = 16; off; off >>= 1) {
        s0 += __shfl_xor_sync(0xffffffffu, s0, off);
        s1 += __shfl_xor_sync(0xffffffffu, s1, off);
    }
    float tw0 = acc0 * (1.f / fmaxf(sqrtf(s0), 1e-12f)) * g_h[kn0 * 64 + 32 + lane];
    float tw1 = acc1 * (1.f / fmaxf(sqrtf(s1), 1e-12f)) * g_h[kn1 * 64 + 32 + lane];
    atomicAdd(&g_agg[(size_t)ji0 * CD + lane], tw0);
    atomicAdd(&g_agg[(size_t)ji1 * CD + lane], tw1);
}

// ---------------- K5b: tbw + lcao (batched butterflies) + scatter ------------
__global__ void __launch_bounds__(256) k5b_edge(const float* __restrict__ W4,
                                                const float* __restrict__ b4,
                                                const int* __restrict__ idx_i) {
    __shared__ __align__(16) float sW4[32 * 36];
    __shared__ __align__(16) float sag[8][32];
    int tid = threadIdx.x;
    for (int idx = tid; idx < 32 * 32; idx += 256) {
        int c = idx / 32, k = idx % 32;
        sW4[c * 36 + k] = W4[idx];
    }
    __syncthreads();
    int w = tid >> 5, lane = tid & 31;
    int e = blockIdx.x * 8 + w;
    if (e >= NE) return;

    // hoist independent gathers to overlap with the agg-dependent GEMM below
    float vv[NORB];
    size_t base = (size_t)e * (NORB * CD);
#pragma unroll
    for (int d = 0; d < NORB; d++)
        vv[d] = __half2float(__ldg(&g_cji_c[base + d * 32 + lane]));
    float nf = __ldg(&g_nf[(size_t)e * CD + lane]);
    float rw[NORB];
#pragma unroll
    for (int d = 0; d < NORB; d++) rw[d] = __ldg(&g_rbw[e * NORB + d]);

    // tbw = silu(agg) @ W4^T + b4
    sag[w][lane] = silu(g_agg[(size_t)e * CD + lane]);
    __syncwarp();
    u64 t2 = 0ull;
#pragma unroll
    for (int k4 = 0; k4 < 8; k4++) {
        ulonglong2 wv = *(const ulonglong2*)&sW4[lane * 36 + k4 * 4];
        ulonglong2 av = *(const ulonglong2*)&sag[w][k4 * 4];
        fma2(t2, av.x, wv.x);
        fma2(t2, av.y, wv.y);
    }
    float tb = 1.f + b4[lane] + unp_sum(t2);

    // lcao: lc[c] = tb[c] * sum_d (rbw[d]/||cji_c[d,:]*tb||) * cji_c[d][c]
    float ss[NORB];
#pragma unroll
    for (int d = 0; d < NORB; d++) {
        float t = vv[d] * tb;
        ss[d] = t * t;
    }
#pragma unroll
    for (int off = 16; off; off >>= 1) {
#pragma unroll
        for (int d = 0; d < NORB; d++)
            ss[d] += __shfl_xor_sync(0xffffffffu, ss[d], off);
    }
    float lc = 0.f;
#pragma unroll
    for (int d = 0; d < NORB; d++) {
        float inv = 1.f / fmaxf(sqrtf(ss[d]), 1e-12f);
        lc = fmaf(rw[d] * inv, vv[d], lc);
    }
    lc *= tb;
    float s = warp_sum(lc * lc);
    lc *= 1.f / fmaxf(sqrtf(s), 1e-12f);

    int ni = idx_i[e];
    atomicAdd(&g_acc[ni * CD + lane], lc * nf);
}

// ---------------- K6: out = x + acc @ W7^T ----------------------------------
__global__ void __launch_bounds__(256) k6_out(const float* __restrict__ x,
                                              const float* __restrict__ W7,
                                              float* __restrict__ out) {
    __shared__ float sW[32 * 128];
    __shared__ float sa[2][32];
    int tid = threadIdx.x;
    for (int idx = tid; idx < 128 * 32; idx += 256) {
        int hc = idx / 32, c = idx % 32;
        sW[c * 128 + hc] = W7[idx];
    }
    int n0 = blockIdx.x * 2;
    if (tid < 64) {
        int r = tid >> 5, c = tid & 31;
        int n = n0 + r;
        if (n < NN) sa[r][c] = g_acc[n * 32 + c];
    }
    __syncthreads();
    int r = tid >> 7, hc = tid & 127;
    int n = n0 + r;
    if (n >= NN) return;
    float acc = x[n * 128 + hc];
#pragma unroll
    for (int c = 0; c < 32; c++) acc = fmaf(sa[r][c], sW[c * 128 + hc], acc);
    out[n * 128 + hc] = acc;
}

// ---------------- host launcher ---------------------------------------------
extern "C" void kernel_launch(void* const* d_in, const int* in_sizes, int n_in,
                              void* d_out, int out_size) {
    int o_ii, o_ij, o_tk, o_ekj, o_eji;
    int o_W1, o_b1, o_W2, o_W3, o_W4, o_b4, o_W5, o_b5, o_W6, o_b6, o_W7;
    if (in_sizes[5] == NE) { // dict order: idx_i at slot 5
        o_ii = 5; o_ij = 6; o_tk = 7; o_ekj = 8; o_eji = 9;
        o_W1 = 10; o_b1 = 11; o_W2 = 12; o_W3 = 13; o_W4 = 14; o_b4 = 15;
        o_W5 = 16; o_b5 = 17; o_W6 = 18; o_b6 = 19; o_W7 = 20;
    } else {                 // signature order: W1 at slot 5
        o_W1 = 5; o_b1 = 6; o_W2 = 7; o_W3 = 8; o_W4 = 9; o_b4 = 10;
        o_W5 = 11; o_b5 = 12; o_W6 = 13; o_b6 = 14; o_W7 = 15;
        o_ii = 16; o_ij = 17; o_tk = 18; o_ekj = 19; o_eji = 20;
    }
    const float* x   = (const float*)d_in[0];
    const float* cji = (const float*)d_in[1];
    const float* cw  = (const float*)d_in[2];
    const float* rb  = (const float*)d_in[3];
    const float* shb = (const float*)d_in[4];
    const int* ii  = (const int*)d_in[o_ii];
    const int* ij  = (const int*)d_in[o_ij];
    const int* tk  = (const int*)d_in[o_tk];
    const int* ekj = (const int*)d_in[o_ekj];
    const int* eji = (const int*)d_in[o_eji];
    const float* W1 = (const float*)d_in[o_W1];
    const float* b1 = (const float*)d_in[o_b1];
    const float* W2 = (const float*)d_in[o_W2];
    const float* W3 = (const float*)d_in[o_W3];
    const float* W4 = (const float*)d_in[o_W4];
    const float* b4 = (const float*)d_in[o_b4];
    const float* W5 = (const float*)d_in[o_W5];
    const float* b5 = (const float*)d_in[o_b5];
    const float* W6 = (const float*)d_in[o_W6];
    const float* b6 = (const float*)d_in[o_b6];
    const float* W7 = (const float*)d_in[o_W7];
    float* out = (float*)d_out;

    // NOTE: k5a moved before k2 (legal: k5a depends only on k1 + indices).
    // This puts k2 in the ncu capture window (4th launch) for next round.
    k0_init<<<(NE * CD + 255) / 256, 256>>>(rb, cw);
    k1_node<<<(NN + 3) / 4, 256>>>(x, W1, b1);
    k5a_nf<<<(NE + 127) / 128, 256>>>(W5, b5, W6, b6, ii, ij);
    k2_mma<<<K2_BLOCKS, 256>>>(cji, W2, W3);
    k3_tri<<<(NT + 15) / 16, 256>>>(shb, ekj, eji, tk);
    k5b_edge<<<(NE + 7) / 8, 256>>>(W4, b4, ii);
    k6_out<<<(NN + 1) / 2, 256>>>(x, W7, out);
}

// round 14
// speedup vs baseline: 1.2184x; 1.0332x over previous
#include <cuda_runtime.h>
#include <cuda_fp16.h>
#include <math.h>

#define NN 10000
#define NE 200000
#define NT 400000
#define NORB 9
#define HD 128
#define CFD 64
#define CD 32
#define R_TOT (NE * NORB)   // 1,800,000 flattened (edge,orb) rows
#define K2_BLOCKS 592       // 148 SMs x 4 resident CTAs

typedef unsigned long long u64;
typedef unsigned int u32;

// ---------------- scratch (device globals; no allocation allowed) ----------
__device__ float g_h[NN * 64];                     // [0:32)=silu(xh), [32:64)=sigm(xk)
__device__ __half g_cji_c[(size_t)NE * NORB * CD]; // 115.2 MB (fp16)
__device__ __half g_ckj_n[(size_t)NE * NORB * CD]; // 115.2 MB (fp16, pre-normalized)
__device__ float g_rbw[NE * NORB];
__device__ float g_agg[(size_t)NE * CD];
__device__ float g_nf[(size_t)NE * CD];            // node-feature MLP output
__device__ float g_acc[NN * CD];

// ---- activations (proven __expf path) ---------------------------------------
__device__ __forceinline__ float sigm(float x) { return 1.f / (1.f + __expf(-x)); }
__device__ __forceinline__ float silu(float x) { return x * sigm(x); }

__device__ __forceinline__ float warp_sum(float s) {
#pragma unroll
    for (int off = 16; off; off >>= 1) s += __shfl_xor_sync(0xffffffffu, s, off);
    return s;
}

// ---- packed fp32x2 FFMA2 (k5b W4 gemm) -------------------------------------
__device__ __forceinline__ void fma2(u64& d, u64 a, u64 b) {
    asm("fma.rn.f32x2 %0,%1,%2,%0;" : "+l"(d) : "l"(a), "l"(b));
}
__device__ __forceinline__ float unp_sum(u64 v) {
    float x, y; asm("mov.b64 {%0,%1},%2;" : "=f"(x), "=f"(y) : "l"(v)); return x + y;
}

// ---- tf32 helpers (k5a) ------------------------------------------------------
__device__ __forceinline__ u32 to_tf32(float f) {
    u32 r; asm("cvt.rna.tf32.f32 %0,%1;" : "=r"(r) : "f"(f)); return r;
}
__device__ __forceinline__ void mma_tf32(float& c0, float& c1, float& c2, float& c3,
                                         u32 a0, u32 a1, u32 a2, u32 a3,
                                         u32 b0, u32 b1) {
    asm("mma.sync.aligned.m16n8k8.row.col.f32.tf32.tf32.f32 "
        "{%0,%1,%2,%3},{%4,%5,%6,%7},{%8,%9},{%0,%1,%2,%3};"
        : "+f"(c0), "+f"(c1), "+f"(c2), "+f"(c3)
        : "r"(a0), "r"(a1), "r"(a2), "r"(a3), "r"(b0), "r"(b1));
}

// ---- fp16 m16n8k16 MMA (k2) -------------------------------------------------
__device__ __forceinline__ void mma_f16(float& c0, float& c1, float& c2, float& c3,
                                        u32 a0, u32 a1, u32 a2, u32 a3,
                                        u32 b0, u32 b1) {
    asm("mma.sync.aligned.m16n8k16.row.col.f32.f16.f16.f32 "
        "{%0,%1,%2,%3},{%4,%5,%6,%7},{%8,%9},{%0,%1,%2,%3};"
        : "+f"(c0), "+f"(c1), "+f"(c2), "+f"(c3)
        : "r"(a0), "r"(a1), "r"(a2), "r"(a3), "r"(b0), "r"(b1));
}
__device__ __forceinline__ u32 h2u(float x, float y) {
    __half2 h = __floats2half2_rn(x, y);
    return *(u32*)&h;
}

// ---------------- K0: zero accumulators + rb_w = rb * cutoff_w -------------
__global__ void k0_init(const float* __restrict__ rb, const float* __restrict__ cw) {
    int i = blockIdx.x * blockDim.x + threadIdx.x;
    if (i < NE * CD) g_agg[i] = 0.f;
    if (i < NN * CD) g_acc[i] = 0.f;
    if (i < NE * NORB) g_rbw[i] = rb[i] * cw[i / NORB];
}

// ---------------- K1: h = x @ W1^T + b1; store silu(xh) / sigm(xk) ----------
__global__ void __launch_bounds__(256) k1_node(const float* __restrict__ x,
                                               const float* __restrict__ W1,
                                               const float* __restrict__ b1) {
    __shared__ float sW[HD * 64];
    __shared__ float sx[4][HD];
    int tid = threadIdx.x;
    for (int idx = tid; idx < 64 * HD; idx += 256) {
        int o = idx / HD, k = idx % HD;
        sW[k * 64 + o] = W1[idx];
    }
    int n0 = blockIdx.x * 4;
#pragma unroll
    for (int r = 0; r < 4; r++) {
        int n = n0 + r;
        if (n < NN)
            for (int k = tid; k < HD; k += 256) sx[r][k] = x[n * HD + k];
    }
    __syncthreads();
    int r = tid / 64, o = tid % 64;
    int n = n0 + r;
    if (n >= NN) return;
    float acc = b1[o];
#pragma unroll 8
    for (int k = 0; k < HD; k++) acc = fmaf(sx[r][k], sW[k * 64 + o], acc);
    g_h[n * 64 + o] = (o < 32) ? silu(acc) : sigm(acc);
}

// ---------------- K2: edge coeff MLP, fp16 m16n8k16 MMA, persistent ----------
// A1 rows: 72 halfs (36 words) pad; A2 rows: 40 halfs (20 words) pad, overlays A1.
// All fragment/staging SMEM patterns are 32-bank conflict-free (word = 4gq+tq /
// 20gq+tq + const).
__global__ void __launch_bounds__(256) k2_mma(const float* __restrict__ cji,
                                              const float* __restrict__ W2,
                                              const float* __restrict__ W3) {
    __shared__ __half sW2h[32 * 72];   // [n][k] pad 72 halfs
    __shared__ __half sW3h[64 * 40];   // [n][k] pad 40 halfs
    __shared__ __half sA1h[8][16 * 72];// per-warp tile; A2 (16x40) overlays
    int tid = threadIdx.x;
    for (int idx = tid; idx < 32 * 64; idx += 256) {
        int n = idx >> 6, k = idx & 63;
        sW2h[n * 72 + k] = __float2half(W2[idx]);
    }
    for (int idx = tid; idx < 64 * 32; idx += 256) {
        int n = idx >> 5, k = idx & 31;
        sW3h[n * 40 + k] = __float2half(W3[idx]);
    }
    __syncthreads();

    int w = tid >> 5, lane = tid & 31;
    int gq = lane >> 2, tq = lane & 3;
    u32* A1 = (u32*)sA1h[w];           // word stride 36 per row
    u32* A2 = (u32*)sA1h[w];           // word stride 20 per row (overlay)
    const u32* W2w = (const u32*)sW2h; // word stride 36
    const u32* W3w = (const u32*)sW3h; // word stride 20

    const int n_tiles = R_TOT / 16;    // 112500 exact
    const int gw0 = blockIdx.x * 8 + w;
    const int gw_stride = K2_BLOCKS * 8;

    for (int tile = gw0; tile < n_tiles; tile += gw_stride) {
        long row0 = (long)tile * 16;

        // stage 16 rows of silu(cji) as fp16 (coalesced float4 per warp)
        for (int i = lane; i < 256; i += 32) {
            int rl = i >> 4, c4 = i & 15;
            float4 f = *(const float4*)(cji + (row0 + rl) * 64 + c4 * 4);
            int wd = rl * 36 + c4 * 2;
            A1[wd]     = h2u(silu(f.x), silu(f.y));
            A1[wd + 1] = h2u(silu(f.z), silu(f.w));
        }
        __syncwarp();

        // GEMM1: C1(16x32) = A1(16x64) @ W2^T, fp16 K=16 per step
        float c1[4][4];
#pragma unroll
        for (int nt = 0; nt < 4; nt++)
#pragma unroll
            for (int j = 0; j < 4; j++) c1[nt][j] = 0.f;
#pragma unroll
        for (int ks = 0; ks < 4; ks++) {            // k0 = ks*16, word kw = ks*8
            int kw = ks * 8;
            u32 a0 = A1[gq * 36 + kw + tq];
            u32 a1 = A1[(gq + 8) * 36 + kw + tq];
            u32 a2 = A1[gq * 36 + kw + tq + 4];
            u32 a3 = A1[(gq + 8) * 36 + kw + tq + 4];
#pragma unroll
            for (int nt = 0; nt < 4; nt++) {
                u32 b0 = W2w[(nt * 8 + gq) * 36 + kw + tq];
                u32 b1 = W2w[(nt * 8 + gq) * 36 + kw + tq + 4];
                mma_f16(c1[nt][0], c1[nt][1], c1[nt][2], c1[nt][3], a0, a1, a2, a3, b0, b1);
            }
        }
        __syncwarp();
        // silu -> A2 fp16 (pack pairs; word = row*20 + nt*4 + tq)
#pragma unroll
        for (int nt = 0; nt < 4; nt++) {
            A2[gq * 20 + nt * 4 + tq]       = h2u(silu(c1[nt][0]), silu(c1[nt][1]));
            A2[(gq + 8) * 20 + nt * 4 + tq] = h2u(silu(c1[nt][2]), silu(c1[nt][3]));
        }
        __syncwarp();

        // GEMM2: C2(16x64) = A2(16x32) @ W3^T, 2 K-steps
        float c2[8][4];
#pragma unroll
        for (int nt = 0; nt < 8; nt++)
#pragma unroll
            for (int j = 0; j < 4; j++) c2[nt][j] = 0.f;
#pragma unroll
        for (int ks = 0; ks < 2; ks++) {            // kw = ks*8
            int kw = ks * 8;
            u32 a0 = A2[gq * 20 + kw + tq];
            u32 a1 = A2[(gq + 8) * 20 + kw + tq];
            u32 a2 = A2[gq * 20 + kw + tq + 4];
            u32 a3 = A2[(gq + 8) * 20 + kw + tq + 4];
#pragma unroll
            for (int nt = 0; nt < 8; nt++) {
                u32 b0 = W3w[(nt * 8 + gq) * 20 + kw + tq];
                u32 b1 = W3w[(nt * 8 + gq) * 20 + kw + tq + 4];
                mma_f16(c2[nt][0], c2[nt][1], c2[nt][2], c2[nt][3], a0, a1, a2, a3, b0, b1);
            }
        }

        // epilogue (C layout identical to tf32 version)
        long rA = row0 + gq, rB = row0 + gq + 8;
#pragma unroll
        for (int nt = 0; nt < 4; nt++) {
            *(__half2*)&g_cji_c[rA * 32 + nt * 8 + 2 * tq] = __floats2half2_rn(c2[nt][0], c2[nt][1]);
            *(__half2*)&g_cji_c[rB * 32 + nt * 8 + 2 * tq] = __floats2half2_rn(c2[nt][2], c2[nt][3]);
        }
        float sa = 0.f, sb = 0.f;
#pragma unroll
        for (int nt = 4; nt < 8; nt++) {
            sa = fmaf(c2[nt][0], c2[nt][0], fmaf(c2[nt][1], c2[nt][1], sa));
            sb = fmaf(c2[nt][2], c2[nt][2], fmaf(c2[nt][3], c2[nt][3], sb));
        }
        sa += __shfl_xor_sync(0xffffffffu, sa, 1);
        sa += __shfl_xor_sync(0xffffffffu, sa, 2);
        sb += __shfl_xor_sync(0xffffffffu, sb, 1);
        sb += __shfl_xor_sync(0xffffffffu, sb, 2);
        float ia = 1.f / fmaxf(sqrtf(sa), 1e-12f);
        float ib = 1.f / fmaxf(sqrtf(sb), 1e-12f);
#pragma unroll
        for (int nt = 4; nt < 8; nt++) {
            *(__half2*)&g_ckj_n[rA * 32 + (nt - 4) * 8 + 2 * tq] =
                __floats2half2_rn(c2[nt][0] * ia, c2[nt][1] * ia);
            *(__half2*)&g_ckj_n[rB * 32 + (nt - 4) * 8 + 2 * tq] =
                __floats2half2_rn(c2[nt][2] * ib, c2[nt][3] * ib);
        }
        __syncwarp();   // protect A1 against next iteration's staging
    }
}

// ---------------- K3: triplets -> edge aggregation, 2 triplets per warp ------
__global__ void __launch_bounds__(256) k3_tri(const float* __restrict__ shb,
                                              const int* __restrict__ e_kj,
                                              const int* __restrict__ e_ji,
                                              const int* __restrict__ t_k) {
    int w = threadIdx.x >> 5, lane = threadIdx.x & 31;
    int t0 = (blockIdx.x * 8 + w) * 2;
    if (t0 >= NT) return;
    int t1 = t0 + 1;
    int kj0 = e_kj[t0], ji0 = e_ji[t0], kn0 = t_k[t0];
    int kj1 = e_kj[t1], ji1 = e_ji[t1], kn1 = t_k[t1];
    float acc0 = 0.f, acc1 = 0.f;
#pragma unroll
    for (int d = 0; d < NORB; d++) {
        float cf0 = __ldg(&g_rbw[kj0 * NORB + d]) * __ldg(&shb[t0 * NORB + d]);
        float cf1 = __ldg(&g_rbw[kj1 * NORB + d]) * __ldg(&shb[t1 * NORB + d]);
        float ck0 = __half2float(__ldg(&g_ckj_n[((size_t)kj0 * NORB + d) * CD + lane]));
        float ck1 = __half2float(__ldg(&g_ckj_n[((size_t)kj1 * NORB + d) * CD + lane]));
        acc0 = fmaf(cf0, ck0, acc0);
        acc1 = fmaf(cf1, ck1, acc1);
    }
    float s0 = acc0 * acc0, s1 = acc1 * acc1;
#pragma unroll
    for (int off = 16; off; off >>= 1) {
        s0 += __shfl_xor_sync(0xffffffffu, s0, off);
        s1 += __shfl_xor_sync(0xffffffffu, s1, off);
    }
    float tw0 = acc0 * (1.f / fmaxf(sqrtf(s0), 1e-12f)) * g_h[kn0 * 64 + 32 + lane];
    float tw1 = acc1 * (1.f / fmaxf(sqrtf(s1), 1e-12f)) * g_h[kn1 * 64 + 32 + lane];
    atomicAdd(&g_agg[(size_t)ji0 * CD + lane], tw0);
    atomicAdd(&g_agg[(size_t)ji1 * CD + lane], tw1);
}

// ---------------- K5a: nf MLP on tensor cores (tf32), A2 aliased on A1 -------
__global__ void __launch_bounds__(256) k5a_nf(const float* __restrict__ W5,
                                              const float* __restrict__ b5,
                                              const float* __restrict__ W6,
                                              const float* __restrict__ b6,
                                              const int* __restrict__ idx_i,
                                              const int* __restrict__ idx_j) {
    __shared__ u32 sW5[32 * 68];
    __shared__ u32 sW6[32 * 36];
    __shared__ float sb5[32], sb6[32];
    __shared__ u32 sA1[8][16 * 68];   // A2 overlays
    int tid = threadIdx.x;
    for (int idx = tid; idx < 32 * 64; idx += 256) {
        int n = idx >> 6, k = idx & 63;
        sW5[n * 68 + k] = to_tf32(W5[idx]);
    }
    for (int idx = tid; idx < 32 * 32; idx += 256) {
        int n = idx >> 5, k = idx & 31;
        sW6[n * 36 + k] = to_tf32(W6[idx]);
    }
    if (tid < 32) { sb5[tid] = b5[tid]; sb6[tid] = b6[tid]; }
    __syncthreads();

    int w = tid >> 5, lane = tid & 31;
    int gq = lane >> 2, tq = lane & 3;
    long row0 = (long)blockIdx.x * 128 + w * 16;
    u32* A1 = sA1[w];
    u32* A2 = sA1[w];

    for (int i = lane; i < 256; i += 32) {
        int rl = i >> 4, c4 = i & 15;
        long e = row0 + rl;
        uint4 v = make_uint4(0u, 0u, 0u, 0u);
        if (e < NE) {
            int n = (c4 < 8) ? __ldg(&idx_i[e]) : __ldg(&idx_j[e]);
            float4 f = *(const float4*)&g_h[n * 64 + (c4 & 7) * 4];
            v.x = to_tf32(f.x); v.y = to_tf32(f.y);
            v.z = to_tf32(f.z); v.w = to_tf32(f.w);
        }
        *(uint4*)&A1[rl * 68 + c4 * 4] = v;
    }
    __syncwarp();

    float c1[4][4];
#pragma unroll
    for (int nt = 0; nt < 4; nt++)
#pragma unroll
        for (int j = 0; j < 4; j++) c1[nt][j] = 0.f;
#pragma unroll
    for (int k0 = 0; k0 < 64; k0 += 8) {
        u32 a0 = A1[gq * 68 + k0 + tq];
        u32 a1 = A1[(gq + 8) * 68 + k0 + tq];
        u32 a2 = A1[gq * 68 + k0 + tq + 4];
        u32 a3 = A1[(gq + 8) * 68 + k0 + tq + 4];
#pragma unroll
        for (int nt = 0; nt < 4; nt++) {
            u32 b0 = sW5[(nt * 8 + gq) * 68 + k0 + tq];
            u32 b1 = sW5[(nt * 8 + gq) * 68 + k0 + tq + 4];
            mma_tf32(c1[nt][0], c1[nt][1], c1[nt][2], c1[nt][3], a0, a1, a2, a3, b0, b1);
        }
    }
    __syncwarp();
#pragma unroll
    for (int nt = 0; nt < 4; nt++) {
        int col = nt * 8 + 2 * tq;
        A2[gq * 36 + col]           = to_tf32(silu(c1[nt][0] + sb5[col]));
        A2[gq * 36 + col + 1]       = to_tf32(silu(c1[nt][1] + sb5[col + 1]));
        A2[(gq + 8) * 36 + col]     = to_tf32(silu(c1[nt][2] + sb5[col]));
        A2[(gq + 8) * 36 + col + 1] = to_tf32(silu(c1[nt][3] + sb5[col + 1]));
    }
    __syncwarp();

    float c2[4][4];
#pragma unroll
    for (int nt = 0; nt < 4; nt++)
#pragma unroll
        for (int j = 0; j < 4; j++) c2[nt][j] = 0.f;
#pragma unroll
    for (int k0 = 0; k0 < 32; k0 += 8) {
        u32 a0 = A2[gq * 36 + k0 + tq];
        u32 a1 = A2[(gq + 8) * 36 + k0 + tq];
        u32 a2 = A2[gq * 36 + k0 + tq + 4];
        u32 a3 = A2[(gq + 8) * 36 + k0 + tq + 4];
#pragma unroll
        for (int nt = 0; nt < 4; nt++) {
            u32 b0 = sW6[(nt * 8 + gq) * 36 + k0 + tq];
            u32 b1 = sW6[(nt * 8 + gq) * 36 + k0 + tq + 4];
            mma_tf32(c2[nt][0], c2[nt][1], c2[nt][2], c2[nt][3], a0, a1, a2, a3, b0, b1);
        }
    }
    long rA = row0 + gq, rB = row0 + gq + 8;
    if (rA < NE) {
#pragma unroll
        for (int nt = 0; nt < 4; nt++) {
            int col = nt * 8 + 2 * tq;
            *(float2*)&g_nf[rA * 32 + col] =
                make_float2(c2[nt][0] + sb6[col], c2[nt][1] + sb6[col + 1]);
        }
    }
    if (rB < NE) {
#pragma unroll
        for (int nt = 0; nt < 4; nt++) {
            int col = nt * 8 + 2 * tq;
            *(float2*)&g_nf[rB * 32 + col] =
                make_float2(c2[nt][2] + sb6[col], c2[nt][3] + sb6[col + 1]);
        }
    }
}

// ---------------- K5b: tbw + lcao (batched butterflies) + scatter ------------
__global__ void __launch_bounds__(256) k5b_edge(const float* __restrict__ W4,
                                                const float* __restrict__ b4,
                                                const int* __restrict__ idx_i) {
    __shared__ __align__(16) float sW4[32 * 36];
    __shared__ __align__(16) float sag[8][32];
    int tid = threadIdx.x;
    for (int idx = tid; idx < 32 * 32; idx += 256) {
        int c = idx / 32, k = idx % 32;
        sW4[c * 36 + k] = W4[idx];
    }
    __syncthreads();
    int w = tid >> 5, lane = tid & 31;
    int e = blockIdx.x * 8 + w;
    if (e >= NE) return;

    float vv[NORB];
    size_t base = (size_t)e * (NORB * CD);
#pragma unroll
    for (int d = 0; d < NORB; d++)
        vv[d] = __half2float(__ldg(&g_cji_c[base + d * 32 + lane]));
    float nf = __ldg(&g_nf[(size_t)e * CD + lane]);
    float rw[NORB];
#pragma unroll
    for (int d = 0; d < NORB; d++) rw[d] = __ldg(&g_rbw[e * NORB + d]);

    sag[w][lane] = silu(g_agg[(size_t)e * CD + lane]);
    __syncwarp();
    u64 t2 = 0ull;
#pragma unroll
    for (int k4 = 0; k4 < 8; k4++) {
        ulonglong2 wv = *(const ulonglong2*)&sW4[lane * 36 + k4 * 4];
        ulonglong2 av = *(const ulonglong2*)&sag[w][k4 * 4];
        fma2(t2, av.x, wv.x);
        fma2(t2, av.y, wv.y);
    }
    float tb = 1.f + b4[lane] + unp_sum(t2);

    float ss[NORB];
#pragma unroll
    for (int d = 0; d < NORB; d++) {
        float t = vv[d] * tb;
        ss[d] = t * t;
    }
#pragma unroll
    for (int off = 16; off; off >>= 1) {
#pragma unroll
        for (int d = 0; d < NORB; d++)
            ss[d] += __shfl_xor_sync(0xffffffffu, ss[d], off);
    }
    float lc = 0.f;
#pragma unroll
    for (int d = 0; d < NORB; d++) {
        float inv = 1.f / fmaxf(sqrtf(ss[d]), 1e-12f);
        lc = fmaf(rw[d] * inv, vv[d], lc);
    }
    lc *= tb;
    float s = warp_sum(lc * lc);
    lc *= 1.f / fmaxf(sqrtf(s), 1e-12f);

    int ni = idx_i[e];
    atomicAdd(&g_acc[ni * CD + lane], lc * nf);
}

// ---------------- K6: out = x + acc @ W7^T ----------------------------------
__global__ void __launch_bounds__(256) k6_out(const float* __restrict__ x,
                                              const float* __restrict__ W7,
                                              float* __restrict__ out) {
    __shared__ float sW[32 * 128];
    __shared__ float sa[2][32];
    int tid = threadIdx.x;
    for (int idx = tid; idx < 128 * 32; idx += 256) {
        int hc = idx / 32, c = idx % 32;
        sW[c * 128 + hc] = W7[idx];
    }
    int n0 = blockIdx.x * 2;
    if (tid < 64) {
        int r = tid >> 5, c = tid & 31;
        int n = n0 + r;
        if (n < NN) sa[r][c] = g_acc[n * 32 + c];
    }
    __syncthreads();
    int r = tid >> 7, hc = tid & 127;
    int n = n0 + r;
    if (n >= NN) return;
    float acc = x[n * 128 + hc];
#pragma unroll
    for (int c = 0; c < 32; c++) acc = fmaf(sa[r][c], sW[c * 128 + hc], acc);
    out[n * 128 + hc] = acc;
}

// ---------------- host launcher ---------------------------------------------
extern "C" void kernel_launch(void* const* d_in, const int* in_sizes, int n_in,
                              void* d_out, int out_size) {
    int o_ii, o_ij, o_tk, o_ekj, o_eji;
    int o_W1, o_b1, o_W2, o_W3, o_W4, o_b4, o_W5, o_b5, o_W6, o_b6, o_W7;
    if (in_sizes[5] == NE) { // dict order: idx_i at slot 5
        o_ii = 5; o_ij = 6; o_tk = 7; o_ekj = 8; o_eji = 9;
        o_W1 = 10; o_b1 = 11; o_W2 = 12; o_W3 = 13; o_W4 = 14; o_b4 = 15;
        o_W5 = 16; o_b5 = 17; o_W6 = 18; o_b6 = 19; o_W7 = 20;
    } else {                 // signature order: W1 at slot 5
        o_W1 = 5; o_b1 = 6; o_W2 = 7; o_W3 = 8; o_W4 = 9; o_b4 = 10;
        o_W5 = 11; o_b5 = 12; o_W6 = 13; o_b6 = 14; o_W7 = 15;
        o_ii = 16; o_ij = 17; o_tk = 18; o_ekj = 19; o_eji = 20;
    }
    const float* x   = (const float*)d_in[0];
    const float* cji = (const float*)d_in[1];
    const float* cw  = (const float*)d_in[2];
    const float* rb  = (const float*)d_in[3];
    const float* shb = (const float*)d_in[4];
    const int* ii  = (const int*)d_in[o_ii];
    const int* ij  = (const int*)d_in[o_ij];
    const int* tk  = (const int*)d_in[o_tk];
    const int* ekj = (const int*)d_in[o_ekj];
    const int* eji = (const int*)d_in[o_eji];
    const float* W1 = (const float*)d_in[o_W1];
    const float* b1 = (const float*)d_in[o_b1];
    const float* W2 = (const float*)d_in[o_W2];
    const float* W3 = (const float*)d_in[o_W3];
    const float* W4 = (const float*)d_in[o_W4];
    const float* b4 = (const float*)d_in[o_b4];
    const float* W5 = (const float*)d_in[o_W5];
    const float* b5 = (const float*)d_in[o_b5];
    const float* W6 = (const float*)d_in[o_W6];
    const float* b6 = (const float*)d_in[o_b6];
    const float* W7 = (const float*)d_in[o_W7];
    float* out = (float*)d_out;

    // Launch order: slot 4 (ncu window) = k3 for next round's triage.
    k0_init<<<(NE * CD + 255) / 256, 256>>>(rb, cw);
    k1_node<<<(NN + 3) / 4, 256>>>(x, W1, b1);
    k2_mma<<<K2_BLOCKS, 256>>>(cji, W2, W3);
    k3_tri<<<(NT + 15) / 16, 256>>>(shb, ekj, eji, tk);
    k5a_nf<<<(NE + 127) / 128, 256>>>(W5, b5, W6, b6, ii, ij);
    k5b_edge<<<(NE + 7) / 8, 256>>>(W4, b4, ii);
    k6_out<<<(NN + 1) / 2, 256>>>(x, W7, out);
}

// round 15
// speedup vs baseline: 1.2438x; 1.0209x over previous
#include <cuda_runtime.h>
#include <cuda_fp16.h>
#include <math.h>

#define NN 10000
#define NE 200000
#define NT 400000
#define NORB 9
#define HD 128
#define CFD 64
#define CD 32
#define R_TOT (NE * NORB)   // 1,800,000 flattened (edge,orb) rows
#define K2_BLOCKS 592       // 148 SMs x 4 resident CTAs
#define K5A_BLOCKS 1563     // ceil(NE/128)
#define K1_BLOCKS 2500      // ceil(NN/4)
#define K0_BLOCKS 25000     // ceil(NE*CD/256)

typedef unsigned long long u64;
typedef unsigned int u32;

// ---------------- scratch (device globals; no allocation allowed) ----------
__device__ float g_h[NN * 64];                     // [0:32)=silu(xh), [32:64)=sigm(xk)
__device__ __half g_cji_c[(size_t)NE * NORB * CD]; // 115.2 MB (fp16)
__device__ __half g_ckj_n[(size_t)NE * NORB * CD]; // 115.2 MB (fp16, pre-normalized)
__device__ float g_rbw[NE * NORB];
__device__ float g_agg[(size_t)NE * CD];
__device__ float g_nf[(size_t)NE * CD];            // node-feature MLP output
__device__ float g_acc[NN * CD];

// ---- activations (proven __expf path) ---------------------------------------
__device__ __forceinline__ float sigm(float x) { return 1.f / (1.f + __expf(-x)); }
__device__ __forceinline__ float silu(float x) { return x * sigm(x); }

__device__ __forceinline__ float warp_sum(float s) {
#pragma unroll
    for (int off = 16; off; off >>= 1) s += __shfl_xor_sync(0xffffffffu, s, off);
    return s;
}

// ---- packed fp32x2 FFMA2 (k5b W4 gemm) -------------------------------------
__device__ __forceinline__ void fma2(u64& d, u64 a, u64 b) {
    asm("fma.rn.f32x2 %0,%1,%2,%0;" : "+l"(d) : "l"(a), "l"(b));
}
__device__ __forceinline__ float unp_sum(u64 v) {
    float x, y; asm("mov.b64 {%0,%1},%2;" : "=f"(x), "=f"(y) : "l"(v)); return x + y;
}

// ---- tf32 helpers (k5a) ------------------------------------------------------
__device__ __forceinline__ u32 to_tf32(float f) {
    u32 r; asm("cvt.rna.tf32.f32 %0,%1;" : "=r"(r) : "f"(f)); return r;
}
__device__ __forceinline__ void mma_tf32(float& c0, float& c1, float& c2, float& c3,
                                         u32 a0, u32 a1, u32 a2, u32 a3,
                                         u32 b0, u32 b1) {
    asm("mma.sync.aligned.m16n8k8.row.col.f32.tf32.tf32.f32 "
        "{%0,%1,%2,%3},{%4,%5,%6,%7},{%8,%9},{%0,%1,%2,%3};"
        : "+f"(c0), "+f"(c1), "+f"(c2), "+f"(c3)
        : "r"(a0), "r"(a1), "r"(a2), "r"(a3), "r"(b0), "r"(b1));
}

// ---- fp16 m16n8k16 MMA (k2) -------------------------------------------------
__device__ __forceinline__ void mma_f16(float& c0, float& c1, float& c2, float& c3,
                                        u32 a0, u32 a1, u32 a2, u32 a3,
                                        u32 b0, u32 b1) {
    asm("mma.sync.aligned.m16n8k16.row.col.f32.f16.f16.f32 "
        "{%0,%1,%2,%3},{%4,%5,%6,%7},{%8,%9},{%0,%1,%2,%3};"
        : "+f"(c0), "+f"(c1), "+f"(c2), "+f"(c3)
        : "r"(a0), "r"(a1), "r"(a2), "r"(a3), "r"(b0), "r"(b1));
}
__device__ __forceinline__ u32 h2u(float x, float y) {
    __half2 h = __floats2half2_rn(x, y);
    return *(u32*)&h;
}

// ---------------- K01: fused init (k0) + node MLP (k1) -----------------------
__global__ void __launch_bounds__(256) k01(const float* __restrict__ rb,
                                           const float* __restrict__ cw,
                                           const float* __restrict__ x,
                                           const float* __restrict__ W1,
                                           const float* __restrict__ b1) {
    __shared__ float sW[HD * 64];
    __shared__ float sx[4][HD];
    int tid = threadIdx.x;
    if (blockIdx.x < K1_BLOCKS) {
        // ---- k1 body ----
        for (int idx = tid; idx < 64 * HD; idx += 256) {
            int o = idx / HD, k = idx % HD;
            sW[k * 64 + o] = W1[idx];
        }
        int n0 = blockIdx.x * 4;
#pragma unroll
        for (int r = 0; r < 4; r++) {
            int n = n0 + r;
            if (n < NN)
                for (int k = tid; k < HD; k += 256) sx[r][k] = x[n * HD + k];
        }
        __syncthreads();
        int r = tid / 64, o = tid % 64;
        int n = n0 + r;
        if (n >= NN) return;
        float acc = b1[o];
#pragma unroll 8
        for (int k = 0; k < HD; k++) acc = fmaf(sx[r][k], sW[k * 64 + o], acc);
        g_h[n * 64 + o] = (o < 32) ? silu(acc) : sigm(acc);
    } else {
        // ---- k0 body ----
        int i = (blockIdx.x - K1_BLOCKS) * 256 + tid;
        if (i < NE * CD) g_agg[i] = 0.f;
        if (i < NN * CD) g_acc[i] = 0.f;
        if (i < NE * NORB) g_rbw[i] = rb[i] * cw[i / NORB];
    }
}

// ---------------- fused K5A (blocks [0,1563)) + K2 (blocks [1563,1563+592)) --
// Shared-memory union (static 48384B): k5a carve is the larger.
__global__ void __launch_bounds__(256, 4) k5a_k2(const float* __restrict__ cji,
                                                 const float* __restrict__ W2,
                                                 const float* __restrict__ W3,
                                                 const float* __restrict__ W5,
                                                 const float* __restrict__ b5,
                                                 const float* __restrict__ W6,
                                                 const float* __restrict__ b6,
                                                 const int* __restrict__ idx_i,
                                                 const int* __restrict__ idx_j) {
    __shared__ __align__(16) char smem[48384];
    int tid = threadIdx.x;
    int w = tid >> 5, lane = tid & 31;
    int gq = lane >> 2, tq = lane & 3;

    if (blockIdx.x < K5A_BLOCKS) {
        // ================= k5a body (tf32) =================
        u32* sW5 = (u32*)smem;                        // 32*68 words
        u32* sW6 = (u32*)(smem + 8704);               // 32*36 words
        float* sb5 = (float*)(smem + 13312);
        float* sb6 = (float*)(smem + 13440);
        u32* sA1w = (u32*)(smem + 13568);             // 8 * 16*68 words
        for (int idx = tid; idx < 32 * 64; idx += 256) {
            int n = idx >> 6, k = idx & 63;
            sW5[n * 68 + k] = to_tf32(W5[idx]);
        }
        for (int idx = tid; idx < 32 * 32; idx += 256) {
            int n = idx >> 5, k = idx & 31;
            sW6[n * 36 + k] = to_tf32(W6[idx]);
        }
        if (tid < 32) { sb5[tid] = b5[tid]; sb6[tid] = b6[tid]; }
        __syncthreads();

        long row0 = (long)blockIdx.x * 128 + w * 16;
        u32* A1 = sA1w + w * (16 * 68);
        u32* A2 = A1;

        for (int i = lane; i < 256; i += 32) {
            int rl = i >> 4, c4 = i & 15;
            long e = row0 + rl;
            uint4 v = make_uint4(0u, 0u, 0u, 0u);
            if (e < NE) {
                int n = (c4 < 8) ? __ldg(&idx_i[e]) : __ldg(&idx_j[e]);
                float4 f = *(const float4*)&g_h[n * 64 + (c4 & 7) * 4];
                v.x = to_tf32(f.x); v.y = to_tf32(f.y);
                v.z = to_tf32(f.z); v.w = to_tf32(f.w);
            }
            *(uint4*)&A1[rl * 68 + c4 * 4] = v;
        }
        __syncwarp();

        float c1[4][4];
#pragma unroll
        for (int nt = 0; nt < 4; nt++)
#pragma unroll
            for (int j = 0; j < 4; j++) c1[nt][j] = 0.f;
#pragma unroll
        for (int k0 = 0; k0 < 64; k0 += 8) {
            u32 a0 = A1[gq * 68 + k0 + tq];
            u32 a1 = A1[(gq + 8) * 68 + k0 + tq];
            u32 a2 = A1[gq * 68 + k0 + tq + 4];
            u32 a3 = A1[(gq + 8) * 68 + k0 + tq + 4];
#pragma unroll
            for (int nt = 0; nt < 4; nt++) {
                u32 b0 = sW5[(nt * 8 + gq) * 68 + k0 + tq];
                u32 b1 = sW5[(nt * 8 + gq) * 68 + k0 + tq + 4];
                mma_tf32(c1[nt][0], c1[nt][1], c1[nt][2], c1[nt][3], a0, a1, a2, a3, b0, b1);
            }
        }
        __syncwarp();
#pragma unroll
        for (int nt = 0; nt < 4; nt++) {
            int col = nt * 8 + 2 * tq;
            A2[gq * 36 + col]           = to_tf32(silu(c1[nt][0] + sb5[col]));
            A2[gq * 36 + col + 1]       = to_tf32(silu(c1[nt][1] + sb5[col + 1]));
            A2[(gq + 8) * 36 + col]     = to_tf32(silu(c1[nt][2] + sb5[col]));
            A2[(gq + 8) * 36 + col + 1] = to_tf32(silu(c1[nt][3] + sb5[col + 1]));
        }
        __syncwarp();

        float c2[4][4];
#pragma unroll
        for (int nt = 0; nt < 4; nt++)
#pragma unroll
            for (int j = 0; j < 4; j++) c2[nt][j] = 0.f;
#pragma unroll
        for (int k0 = 0; k0 < 32; k0 += 8) {
            u32 a0 = A2[gq * 36 + k0 + tq];
            u32 a1 = A2[(gq + 8) * 36 + k0 + tq];
            u32 a2 = A2[gq * 36 + k0 + tq + 4];
            u32 a3 = A2[(gq + 8) * 36 + k0 + tq + 4];
#pragma unroll
            for (int nt = 0; nt < 4; nt++) {
                u32 b0 = sW6[(nt * 8 + gq) * 36 + k0 + tq];
                u32 b1 = sW6[(nt * 8 + gq) * 36 + k0 + tq + 4];
                mma_tf32(c2[nt][0], c2[nt][1], c2[nt][2], c2[nt][3], a0, a1, a2, a3, b0, b1);
            }
        }
        long rA = row0 + gq, rB = row0 + gq + 8;
        if (rA < NE) {
#pragma unroll
            for (int nt = 0; nt < 4; nt++) {
                int col = nt * 8 + 2 * tq;
                *(float2*)&g_nf[rA * 32 + col] =
                    make_float2(c2[nt][0] + sb6[col], c2[nt][1] + sb6[col + 1]);
            }
        }
        if (rB < NE) {
#pragma unroll
            for (int nt = 0; nt < 4; nt++) {
                int col = nt * 8 + 2 * tq;
                *(float2*)&g_nf[rB * 32 + col] =
                    make_float2(c2[nt][2] + sb6[col], c2[nt][3] + sb6[col + 1]);
            }
        }
    } else {
        // ================= k2 body (fp16, persistent) =================
        __half* sW2h = (__half*)smem;                 // 32*72 halfs (4608B)
        __half* sW3h = (__half*)(smem + 4608);        // 64*40 halfs (5120B)
        __half* sA1h = (__half*)(smem + 9728);        // 8 * 16*72 halfs (18432B)
        for (int idx = tid; idx < 32 * 64; idx += 256) {
            int n = idx >> 6, k = idx & 63;
            sW2h[n * 72 + k] = __float2half(W2[idx]);
        }
        for (int idx = tid; idx < 64 * 32; idx += 256) {
            int n = idx >> 5, k = idx & 31;
            sW3h[n * 40 + k] = __float2half(W3[idx]);
        }
        __syncthreads();

        u32* A1 = (u32*)(sA1h + w * (16 * 72));       // word stride 36 per row
        u32* A2 = A1;                                  // word stride 20 (overlay)
        const u32* W2w = (const u32*)sW2h;            // word stride 36
        const u32* W3w = (const u32*)sW3h;            // word stride 20

        const int n_tiles = R_TOT / 16;
        const int gw0 = (blockIdx.x - K5A_BLOCKS) * 8 + w;
        const int gw_stride = K2_BLOCKS * 8;

        for (int tile = gw0; tile < n_tiles; tile += gw_stride) {
            long row0 = (long)tile * 16;
            for (int i = lane; i < 256; i += 32) {
                int rl = i >> 4, c4 = i & 15;
                float4 f = *(const float4*)(cji + (row0 + rl) * 64 + c4 * 4);
                int wd = rl * 36 + c4 * 2;
                A1[wd]     = h2u(silu(f.x), silu(f.y));
                A1[wd + 1] = h2u(silu(f.z), silu(f.w));
            }
            __syncwarp();

            float c1[4][4];
#pragma unroll
            for (int nt = 0; nt < 4; nt++)
#pragma unroll
                for (int j = 0; j < 4; j++) c1[nt][j] = 0.f;
#pragma unroll
            for (int ks = 0; ks < 4; ks++) {
                int kw = ks * 8;
                u32 a0 = A1[gq * 36 + kw + tq];
                u32 a1 = A1[(gq + 8) * 36 + kw + tq];
                u32 a2 = A1[gq * 36 + kw + tq + 4];
                u32 a3 = A1[(gq + 8) * 36 + kw + tq + 4];
#pragma unroll
                for (int nt = 0; nt < 4; nt++) {
                    u32 b0 = W2w[(nt * 8 + gq) * 36 + kw + tq];
                    u32 b1 = W2w[(nt * 8 + gq) * 36 + kw + tq + 4];
                    mma_f16(c1[nt][0], c1[nt][1], c1[nt][2], c1[nt][3], a0, a1, a2, a3, b0, b1);
                }
            }
            __syncwarp();
#pragma unroll
            for (int nt = 0; nt < 4; nt++) {
                A2[gq * 20 + nt * 4 + tq]       = h2u(silu(c1[nt][0]), silu(c1[nt][1]));
                A2[(gq + 8) * 20 + nt * 4 + tq] = h2u(silu(c1[nt][2]), silu(c1[nt][3]));
            }
            __syncwarp();

            float c2[8][4];
#pragma unroll
            for (int nt = 0; nt < 8; nt++)
#pragma unroll
                for (int j = 0; j < 4; j++) c2[nt][j] = 0.f;
#pragma unroll
            for (int ks = 0; ks < 2; ks++) {
                int kw = ks * 8;
                u32 a0 = A2[gq * 20 + kw + tq];
                u32 a1 = A2[(gq + 8) * 20 + kw + tq];
                u32 a2 = A2[gq * 20 + kw + tq + 4];
                u32 a3 = A2[(gq + 8) * 20 + kw + tq + 4];
#pragma unroll
                for (int nt = 0; nt < 8; nt++) {
                    u32 b0 = W3w[(nt * 8 + gq) * 20 + kw + tq];
                    u32 b1 = W3w[(nt * 8 + gq) * 20 + kw + tq + 4];
                    mma_f16(c2[nt][0], c2[nt][1], c2[nt][2], c2[nt][3], a0, a1, a2, a3, b0, b1);
                }
            }

            long rA = row0 + gq, rB = row0 + gq + 8;
#pragma unroll
            for (int nt = 0; nt < 4; nt++) {
                *(__half2*)&g_cji_c[rA * 32 + nt * 8 + 2 * tq] = __floats2half2_rn(c2[nt][0], c2[nt][1]);
                *(__half2*)&g_cji_c[rB * 32 + nt * 8 + 2 * tq] = __floats2half2_rn(c2[nt][2], c2[nt][3]);
            }
            float sa = 0.f, sb = 0.f;
#pragma unroll
            for (int nt = 4; nt < 8; nt++) {
                sa = fmaf(c2[nt][0], c2[nt][0], fmaf(c2[nt][1], c2[nt][1], sa));
                sb = fmaf(c2[nt][2], c2[nt][2], fmaf(c2[nt][3], c2[nt][3], sb));
            }
            sa += __shfl_xor_sync(0xffffffffu, sa, 1);
            sa += __shfl_xor_sync(0xffffffffu, sa, 2);
            sb += __shfl_xor_sync(0xffffffffu, sb, 1);
            sb += __shfl_xor_sync(0xffffffffu, sb, 2);
            float ia = 1.f / fmaxf(sqrtf(sa), 1e-12f);
            float ib = 1.f / fmaxf(sqrtf(sb), 1e-12f);
#pragma unroll
            for (int nt = 4; nt < 8; nt++) {
                *(__half2*)&g_ckj_n[rA * 32 + (nt - 4) * 8 + 2 * tq] =
                    __floats2half2_rn(c2[nt][0] * ia, c2[nt][1] * ia);
                *(__half2*)&g_ckj_n[rB * 32 + (nt - 4) * 8 + 2 * tq] =
                    __floats2half2_rn(c2[nt][2] * ib, c2[nt][3] * ib);
            }
            __syncwarp();
        }
    }
}

// ---------------- K3: triplets -> edge aggregation, 2 triplets per warp ------
__global__ void __launch_bounds__(256) k3_tri(const float* __restrict__ shb,
                                              const int* __restrict__ e_kj,
                                              const int* __restrict__ e_ji,
                                              const int* __restrict__ t_k) {
    int w = threadIdx.x >> 5, lane = threadIdx.x & 31;
    int t0 = (blockIdx.x * 8 + w) * 2;
    if (t0 >= NT) return;
    int t1 = t0 + 1;
    int kj0 = e_kj[t0], ji0 = e_ji[t0], kn0 = t_k[t0];
    int kj1 = e_kj[t1], ji1 = e_ji[t1], kn1 = t_k[t1];
    float acc0 = 0.f, acc1 = 0.f;
#pragma unroll
    for (int d = 0; d < NORB; d++) {
        float cf0 = __ldg(&g_rbw[kj0 * NORB + d]) * __ldg(&shb[t0 * NORB + d]);
        float cf1 = __ldg(&g_rbw[kj1 * NORB + d]) * __ldg(&shb[t1 * NORB + d]);
        float ck0 = __half2float(__ldg(&g_ckj_n[((size_t)kj0 * NORB + d) * CD + lane]));
        float ck1 = __half2float(__ldg(&g_ckj_n[((size_t)kj1 * NORB + d) * CD + lane]));
        acc0 = fmaf(cf0, ck0, acc0);
        acc1 = fmaf(cf1, ck1, acc1);
    }
    float s0 = acc0 * acc0, s1 = acc1 * acc1;
#pragma unroll
    for (int off = 16; off; off >>= 1) {
        s0 += __shfl_xor_sync(0xffffffffu, s0, off);
        s1 += __shfl_xor_sync(0xffffffffu, s1, off);
    }
    float tw0 = acc0 * (1.f / fmaxf(sqrtf(s0), 1e-12f)) * g_h[kn0 * 64 + 32 + lane];
    float tw1 = acc1 * (1.f / fmaxf(sqrtf(s1), 1e-12f)) * g_h[kn1 * 64 + 32 + lane];
    atomicAdd(&g_agg[(size_t)ji0 * CD + lane], tw0);
    atomicAdd(&g_agg[(size_t)ji1 * CD + lane], tw1);
}

// ---------------- K5b: tbw + lcao (batched butterflies) + scatter ------------
__global__ void __launch_bounds__(256) k5b_edge(const float* __restrict__ W4,
                                                const float* __restrict__ b4,
                                                const int* __restrict__ idx_i) {
    __shared__ __align__(16) float sW4[32 * 36];
    __shared__ __align__(16) float sag[8][32];
    int tid = threadIdx.x;
    for (int idx = tid; idx < 32 * 32; idx += 256) {
        int c = idx / 32, k = idx % 32;
        sW4[c * 36 + k] = W4[idx];
    }
    __syncthreads();
    int w = tid >> 5, lane = tid & 31;
    int e = blockIdx.x * 8 + w;
    if (e >= NE) return;

    float vv[NORB];
    size_t base = (size_t)e * (NORB * CD);
#pragma unroll
    for (int d = 0; d < NORB; d++)
        vv[d] = __half2float(__ldg(&g_cji_c[base + d * 32 + lane]));
    float nf = __ldg(&g_nf[(size_t)e * CD + lane]);
    float rw[NORB];
#pragma unroll
    for (int d = 0; d < NORB; d++) rw[d] = __ldg(&g_rbw[e * NORB + d]);

    sag[w][lane] = silu(g_agg[(size_t)e * CD + lane]);
    __syncwarp();
    u64 t2 = 0ull;
#pragma unroll
    for (int k4 = 0; k4 < 8; k4++) {
        ulonglong2 wv = *(const ulonglong2*)&sW4[lane * 36 + k4 * 4];
        ulonglong2 av = *(const ulonglong2*)&sag[w][k4 * 4];
        fma2(t2, av.x, wv.x);
        fma2(t2, av.y, wv.y);
    }
    float tb = 1.f + b4[lane] + unp_sum(t2);

    float ss[NORB];
#pragma unroll
    for (int d = 0; d < NORB; d++) {
        float t = vv[d] * tb;
        ss[d] = t * t;
    }
#pragma unroll
    for (int off = 16; off; off >>= 1) {
#pragma unroll
        for (int d = 0; d < NORB; d++)
            ss[d] += __shfl_xor_sync(0xffffffffu, ss[d], off);
    }
    float lc = 0.f;
#pragma unroll
    for (int d = 0; d < NORB; d++) {
        float inv = 1.f / fmaxf(sqrtf(ss[d]), 1e-12f);
        lc = fmaf(rw[d] * inv, vv[d], lc);
    }
    lc *= tb;
    float s = warp_sum(lc * lc);
    lc *= 1.f / fmaxf(sqrtf(s), 1e-12f);

    int ni = idx_i[e];
    atomicAdd(&g_acc[ni * CD + lane], lc * nf);
}

// ---------------- K6: out = x + acc @ W7^T ----------------------------------
__global__ void __launch_bounds__(256) k6_out(const float* __restrict__ x,
                                              const float* __restrict__ W7,
                                              float* __restrict__ out) {
    __shared__ float sW[32 * 128];
    __shared__ float sa[2][32];
    int tid = threadIdx.x;
    for (int idx = tid; idx < 128 * 32; idx += 256) {
        int hc = idx / 32, c = idx % 32;
        sW[c * 128 + hc] = W7[idx];
    }
    int n0 = blockIdx.x * 2;
    if (tid < 64) {
        int r = tid >> 5, c = tid & 31;
        int n = n0 + r;
        if (n < NN) sa[r][c] = g_acc[n * 32 + c];
    }
    __syncthreads();
    int r = tid >> 7, hc = tid & 127;
    int n = n0 + r;
    if (n >= NN) return;
    float acc = x[n * 128 + hc];
#pragma unroll
    for (int c = 0; c < 32; c++) acc = fmaf(sa[r][c], sW[c * 128 + hc], acc);
    out[n * 128 + hc] = acc;
}

// ---------------- host launcher ---------------------------------------------
extern "C" void kernel_launch(void* const* d_in, const int* in_sizes, int n_in,
                              void* d_out, int out_size) {
    int o_ii, o_ij, o_tk, o_ekj, o_eji;
    int o_W1, o_b1, o_W2, o_W3, o_W4, o_b4, o_W5, o_b5, o_W6, o_b6, o_W7;
    if (in_sizes[5] == NE) { // dict order: idx_i at slot 5
        o_ii = 5; o_ij = 6; o_tk = 7; o_ekj = 8; o_eji = 9;
        o_W1 = 10; o_b1 = 11; o_W2 = 12; o_W3 = 13; o_W4 = 14; o_b4 = 15;
        o_W5 = 16; o_b5 = 17; o_W6 = 18; o_b6 = 19; o_W7 = 20;
    } else {                 // signature order: W1 at slot 5
        o_W1 = 5; o_b1 = 6; o_W2 = 7; o_W3 = 8; o_W4 = 9; o_b4 = 10;
        o_W5 = 11; o_b5 = 12; o_W6 = 13; o_b6 = 14; o_W7 = 15;
        o_ii = 16; o_ij = 17; o_tk = 18; o_ekj = 19; o_eji = 20;
    }
    const float* x   = (const float*)d_in[0];
    const float* cji = (const float*)d_in[1];
    const float* cw  = (const float*)d_in[2];
    const float* rb  = (const float*)d_in[3];
    const float* shb = (const float*)d_in[4];
    const int* ii  = (const int*)d_in[o_ii];
    const int* ij  = (const int*)d_in[o_ij];
    const int* tk  = (const int*)d_in[o_tk];
    const int* ekj = (const int*)d_in[o_ekj];
    const int* eji = (const int*)d_in[o_eji];
    const float* W1 = (const float*)d_in[o_W1];
    const float* b1 = (const float*)d_in[o_b1];
    const float* W2 = (const float*)d_in[o_W2];
    const float* W3 = (const float*)d_in[o_W3];
    const float* W4 = (const float*)d_in[o_W4];
    const float* b4 = (const float*)d_in[o_b4];
    const float* W5 = (const float*)d_in[o_W5];
    const float* b5 = (const float*)d_in[o_b5];
    const float* W6 = (const float*)d_in[o_W6];
    const float* b6 = (const float*)d_in[o_b6];
    const float* W7 = (const float*)d_in[o_W7];
    float* out = (float*)d_out;

    // 5 launches; slot 4 (ncu window) = k5b.
    k01<<<K1_BLOCKS + K0_BLOCKS, 256>>>(rb, cw, x, W1, b1);
    k5a_k2<<<K5A_BLOCKS + K2_BLOCKS, 256>>>(cji, W2, W3, W5, b5, W6, b6, ii, ij);
    k3_tri<<<(NT + 15) / 16, 256>>>(shb, ekj, eji, tk);
    k5b_edge<<<(NE + 7) / 8, 256>>>(W4, b4, ii);
    k6_out<<<(NN + 1) / 2, 256>>>(x, W7, out);
}

// round 16
// speedup vs baseline: 1.2990x; 1.0444x over previous
#include <cuda_runtime.h>
#include <cuda_fp16.h>
#include <math.h>

#define NN 10000
#define NE 200000
#define NT 400000
#define NORB 9
#define HD 128
#define CFD 64
#define CD 32
#define R_TOT (NE * NORB)   // 1,800,000 flattened (edge,orb) rows
#define K2_BLOCKS 592       // 148 SMs x 4 resident CTAs
#define K5A_BLOCKS 1563     // ceil(NE/128)
#define K1_BLOCKS 2500      // ceil(NN/4)
#define K0_BLOCKS 25000     // ceil(NE*CD/256)

typedef unsigned long long u64;
typedef unsigned int u32;

// ---------------- scratch (device globals; no allocation allowed) ----------
__device__ float g_h[NN * 64];                     // [0:32)=silu(xh), [32:64)=sigm(xk)
__device__ __half g_cji_c[(size_t)NE * NORB * CD]; // 115.2 MB (fp16)
__device__ __half g_ckj_n[(size_t)NE * NORB * CD]; // 115.2 MB (fp16, pre-normalized)
__device__ float g_rbw[NE * NORB];
__device__ float g_agg[(size_t)NE * CD];
__device__ float g_nf[(size_t)NE * CD];            // node-feature MLP output
__device__ float g_acc[NN * CD];

// ---- activations (proven __expf path) ---------------------------------------
__device__ __forceinline__ float sigm(float x) { return 1.f / (1.f + __expf(-x)); }
__device__ __forceinline__ float silu(float x) { return x * sigm(x); }

__device__ __forceinline__ float warp_sum(float s) {
#pragma unroll
    for (int off = 16; off; off >>= 1) s += __shfl_xor_sync(0xffffffffu, s, off);
    return s;
}

// ---- tf32 helpers ------------------------------------------------------------
__device__ __forceinline__ u32 to_tf32(float f) {
    u32 r; asm("cvt.rna.tf32.f32 %0,%1;" : "=r"(r) : "f"(f)); return r;
}
__device__ __forceinline__ void mma_tf32(float& c0, float& c1, float& c2, float& c3,
                                         u32 a0, u32 a1, u32 a2, u32 a3,
                                         u32 b0, u32 b1) {
    asm("mma.sync.aligned.m16n8k8.row.col.f32.tf32.tf32.f32 "
        "{%0,%1,%2,%3},{%4,%5,%6,%7},{%8,%9},{%0,%1,%2,%3};"
        : "+f"(c0), "+f"(c1), "+f"(c2), "+f"(c3)
        : "r"(a0), "r"(a1), "r"(a2), "r"(a3), "r"(b0), "r"(b1));
}

// ---- fp16 m16n8k16 MMA (k2) -------------------------------------------------
__device__ __forceinline__ void mma_f16(float& c0, float& c1, float& c2, float& c3,
                                        u32 a0, u32 a1, u32 a2, u32 a3,
                                        u32 b0, u32 b1) {
    asm("mma.sync.aligned.m16n8k16.row.col.f32.f16.f16.f32 "
        "{%0,%1,%2,%3},{%4,%5,%6,%7},{%8,%9},{%0,%1,%2,%3};"
        : "+f"(c0), "+f"(c1), "+f"(c2), "+f"(c3)
        : "r"(a0), "r"(a1), "r"(a2), "r"(a3), "r"(b0), "r"(b1));
}
__device__ __forceinline__ u32 h2u(float x, float y) {
    __half2 h = __floats2half2_rn(x, y);
    return *(u32*)&h;
}

// ---------------- K01: fused init (k0) + node MLP (k1) -----------------------
__global__ void __launch_bounds__(256) k01(const float* __restrict__ rb,
                                           const float* __restrict__ cw,
                                           const float* __restrict__ x,
                                           const float* __restrict__ W1,
                                           const float* __restrict__ b1) {
    __shared__ float sW[HD * 64];
    __shared__ float sx[4][HD];
    int tid = threadIdx.x;
    if (blockIdx.x < K1_BLOCKS) {
        for (int idx = tid; idx < 64 * HD; idx += 256) {
            int o = idx / HD, k = idx % HD;
            sW[k * 64 + o] = W1[idx];
        }
        int n0 = blockIdx.x * 4;
#pragma unroll
        for (int r = 0; r < 4; r++) {
            int n = n0 + r;
            if (n < NN)
                for (int k = tid; k < HD; k += 256) sx[r][k] = x[n * HD + k];
        }
        __syncthreads();
        int r = tid / 64, o = tid % 64;
        int n = n0 + r;
        if (n >= NN) return;
        float acc = b1[o];
#pragma unroll 8
        for (int k = 0; k < HD; k++) acc = fmaf(sx[r][k], sW[k * 64 + o], acc);
        g_h[n * 64 + o] = (o < 32) ? silu(acc) : sigm(acc);
    } else {
        int i = (blockIdx.x - K1_BLOCKS) * 256 + tid;
        if (i < NE * CD) g_agg[i] = 0.f;
        if (i < NN * CD) g_acc[i] = 0.f;
        if (i < NE * NORB) g_rbw[i] = rb[i] * cw[i / NORB];
    }
}

// ---------------- fused K5A (blocks [0,1563)) + K2 (blocks [1563,2155)) ------
__global__ void __launch_bounds__(256, 4) k5a_k2(const float* __restrict__ cji,
                                                 const float* __restrict__ W2,
                                                 const float* __restrict__ W3,
                                                 const float* __restrict__ W5,
                                                 const float* __restrict__ b5,
                                                 const float* __restrict__ W6,
                                                 const float* __restrict__ b6,
                                                 const int* __restrict__ idx_i,
                                                 const int* __restrict__ idx_j) {
    __shared__ __align__(16) char smem[48384];
    int tid = threadIdx.x;
    int w = tid >> 5, lane = tid & 31;
    int gq = lane >> 2, tq = lane & 3;

    if (blockIdx.x < K5A_BLOCKS) {
        // ================= k5a body (tf32) =================
        u32* sW5 = (u32*)smem;
        u32* sW6 = (u32*)(smem + 8704);
        float* sb5 = (float*)(smem + 13312);
        float* sb6 = (float*)(smem + 13440);
        u32* sA1w = (u32*)(smem + 13568);
        for (int idx = tid; idx < 32 * 64; idx += 256) {
            int n = idx >> 6, k = idx & 63;
            sW5[n * 68 + k] = to_tf32(W5[idx]);
        }
        for (int idx = tid; idx < 32 * 32; idx += 256) {
            int n = idx >> 5, k = idx & 31;
            sW6[n * 36 + k] = to_tf32(W6[idx]);
        }
        if (tid < 32) { sb5[tid] = b5[tid]; sb6[tid] = b6[tid]; }
        __syncthreads();

        long row0 = (long)blockIdx.x * 128 + w * 16;
        u32* A1 = sA1w + w * (16 * 68);
        u32* A2 = A1;

        for (int i = lane; i < 256; i += 32) {
            int rl = i >> 4, c4 = i & 15;
            long e = row0 + rl;
            uint4 v = make_uint4(0u, 0u, 0u, 0u);
            if (e < NE) {
                int n = (c4 < 8) ? __ldg(&idx_i[e]) : __ldg(&idx_j[e]);
                float4 f = *(const float4*)&g_h[n * 64 + (c4 & 7) * 4];
                v.x = to_tf32(f.x); v.y = to_tf32(f.y);
                v.z = to_tf32(f.z); v.w = to_tf32(f.w);
            }
            *(uint4*)&A1[rl * 68 + c4 * 4] = v;
        }
        __syncwarp();

        float c1[4][4];
#pragma unroll
        for (int nt = 0; nt < 4; nt++)
#pragma unroll
            for (int j = 0; j < 4; j++) c1[nt][j] = 0.f;
#pragma unroll
        for (int k0 = 0; k0 < 64; k0 += 8) {
            u32 a0 = A1[gq * 68 + k0 + tq];
            u32 a1 = A1[(gq + 8) * 68 + k0 + tq];
            u32 a2 = A1[gq * 68 + k0 + tq + 4];
            u32 a3 = A1[(gq + 8) * 68 + k0 + tq + 4];
#pragma unroll
            for (int nt = 0; nt < 4; nt++) {
                u32 b0 = sW5[(nt * 8 + gq) * 68 + k0 + tq];
                u32 b1 = sW5[(nt * 8 + gq) * 68 + k0 + tq + 4];
                mma_tf32(c1[nt][0], c1[nt][1], c1[nt][2], c1[nt][3], a0, a1, a2, a3, b0, b1);
            }
        }
        __syncwarp();
#pragma unroll
        for (int nt = 0; nt < 4; nt++) {
            int col = nt * 8 + 2 * tq;
            A2[gq * 36 + col]           = to_tf32(silu(c1[nt][0] + sb5[col]));
            A2[gq * 36 + col + 1]       = to_tf32(silu(c1[nt][1] + sb5[col + 1]));
            A2[(gq + 8) * 36 + col]     = to_tf32(silu(c1[nt][2] + sb5[col]));
            A2[(gq + 8) * 36 + col + 1] = to_tf32(silu(c1[nt][3] + sb5[col + 1]));
        }
        __syncwarp();

        float c2[4][4];
#pragma unroll
        for (int nt = 0; nt < 4; nt++)
#pragma unroll
            for (int j = 0; j < 4; j++) c2[nt][j] = 0.f;
#pragma unroll
        for (int k0 = 0; k0 < 32; k0 += 8) {
            u32 a0 = A2[gq * 36 + k0 + tq];
            u32 a1 = A2[(gq + 8) * 36 + k0 + tq];
            u32 a2 = A2[gq * 36 + k0 + tq + 4];
            u32 a3 = A2[(gq + 8) * 36 + k0 + tq + 4];
#pragma unroll
            for (int nt = 0; nt < 4; nt++) {
                u32 b0 = sW6[(nt * 8 + gq) * 36 + k0 + tq];
                u32 b1 = sW6[(nt * 8 + gq) * 36 + k0 + tq + 4];
                mma_tf32(c2[nt][0], c2[nt][1], c2[nt][2], c2[nt][3], a0, a1, a2, a3, b0, b1);
            }
        }
        long rA = row0 + gq, rB = row0 + gq + 8;
        if (rA < NE) {
#pragma unroll
            for (int nt = 0; nt < 4; nt++) {
                int col = nt * 8 + 2 * tq;
                *(float2*)&g_nf[rA * 32 + col] =
                    make_float2(c2[nt][0] + sb6[col], c2[nt][1] + sb6[col + 1]);
            }
        }
        if (rB < NE) {
#pragma unroll
            for (int nt = 0; nt < 4; nt++) {
                int col = nt * 8 + 2 * tq;
                *(float2*)&g_nf[rB * 32 + col] =
                    make_float2(c2[nt][2] + sb6[col], c2[nt][3] + sb6[col + 1]);
            }
        }
    } else {
        // ================= k2 body (fp16, persistent) =================
        __half* sW2h = (__half*)smem;
        __half* sW3h = (__half*)(smem + 4608);
        __half* sA1h = (__half*)(smem + 9728);
        for (int idx = tid; idx < 32 * 64; idx += 256) {
            int n = idx >> 6, k = idx & 63;
            sW2h[n * 72 + k] = __float2half(W2[idx]);
        }
        for (int idx = tid; idx < 64 * 32; idx += 256) {
            int n = idx >> 5, k = idx & 31;
            sW3h[n * 40 + k] = __float2half(W3[idx]);
        }
        __syncthreads();

        u32* A1 = (u32*)(sA1h + w * (16 * 72));
        u32* A2 = A1;
        const u32* W2w = (const u32*)sW2h;
        const u32* W3w = (const u32*)sW3h;

        const int n_tiles = R_TOT / 16;
        const int gw0 = (blockIdx.x - K5A_BLOCKS) * 8 + w;
        const int gw_stride = K2_BLOCKS * 8;

        for (int tile = gw0; tile < n_tiles; tile += gw_stride) {
            long row0 = (long)tile * 16;
            for (int i = lane; i < 256; i += 32) {
                int rl = i >> 4, c4 = i & 15;
                float4 f = *(const float4*)(cji + (row0 + rl) * 64 + c4 * 4);
                int wd = rl * 36 + c4 * 2;
                A1[wd]     = h2u(silu(f.x), silu(f.y));
                A1[wd + 1] = h2u(silu(f.z), silu(f.w));
            }
            __syncwarp();

            float c1[4][4];
#pragma unroll
            for (int nt = 0; nt < 4; nt++)
#pragma unroll
                for (int j = 0; j < 4; j++) c1[nt][j] = 0.f;
#pragma unroll
            for (int ks = 0; ks < 4; ks++) {
                int kw = ks * 8;
                u32 a0 = A1[gq * 36 + kw + tq];
                u32 a1 = A1[(gq + 8) * 36 + kw + tq];
                u32 a2 = A1[gq * 36 + kw + tq + 4];
                u32 a3 = A1[(gq + 8) * 36 + kw + tq + 4];
#pragma unroll
                for (int nt = 0; nt < 4; nt++) {
                    u32 b0 = W2w[(nt * 8 + gq) * 36 + kw + tq];
                    u32 b1 = W2w[(nt * 8 + gq) * 36 + kw + tq + 4];
                    mma_f16(c1[nt][0], c1[nt][1], c1[nt][2], c1[nt][3], a0, a1, a2, a3, b0, b1);
                }
            }
            __syncwarp();
#pragma unroll
            for (int nt = 0; nt < 4; nt++) {
                A2[gq * 20 + nt * 4 + tq]       = h2u(silu(c1[nt][0]), silu(c1[nt][1]));
                A2[(gq + 8) * 20 + nt * 4 + tq] = h2u(silu(c1[nt][2]), silu(c1[nt][3]));
            }
            __syncwarp();

            float c2[8][4];
#pragma unroll
            for (int nt = 0; nt < 8; nt++)
#pragma unroll
                for (int j = 0; j < 4; j++) c2[nt][j] = 0.f;
#pragma unroll
            for (int ks = 0; ks < 2; ks++) {
                int kw = ks * 8;
                u32 a0 = A2[gq * 20 + kw + tq];
                u32 a1 = A2[(gq + 8) * 20 + kw + tq];
                u32 a2 = A2[gq * 20 + kw + tq + 4];
                u32 a3 = A2[(gq + 8) * 20 + kw + tq + 4];
#pragma unroll
                for (int nt = 0; nt < 8; nt++) {
                    u32 b0 = W3w[(nt * 8 + gq) * 20 + kw + tq];
                    u32 b1 = W3w[(nt * 8 + gq) * 20 + kw + tq + 4];
                    mma_f16(c2[nt][0], c2[nt][1], c2[nt][2], c2[nt][3], a0, a1, a2, a3, b0, b1);
                }
            }

            long rA = row0 + gq, rB = row0 + gq + 8;
#pragma unroll
            for (int nt = 0; nt < 4; nt++) {
                *(__half2*)&g_cji_c[rA * 32 + nt * 8 + 2 * tq] = __floats2half2_rn(c2[nt][0], c2[nt][1]);
                *(__half2*)&g_cji_c[rB * 32 + nt * 8 + 2 * tq] = __floats2half2_rn(c2[nt][2], c2[nt][3]);
            }
            float sa = 0.f, sb = 0.f;
#pragma unroll
            for (int nt = 4; nt < 8; nt++) {
                sa = fmaf(c2[nt][0], c2[nt][0], fmaf(c2[nt][1], c2[nt][1], sa));
                sb = fmaf(c2[nt][2], c2[nt][2], fmaf(c2[nt][3], c2[nt][3], sb));
            }
            sa += __shfl_xor_sync(0xffffffffu, sa, 1);
            sa += __shfl_xor_sync(0xffffffffu, sa, 2);
            sb += __shfl_xor_sync(0xffffffffu, sb, 1);
            sb += __shfl_xor_sync(0xffffffffu, sb, 2);
            float ia = 1.f / fmaxf(sqrtf(sa), 1e-12f);
            float ib = 1.f / fmaxf(sqrtf(sb), 1e-12f);
#pragma unroll
            for (int nt = 4; nt < 8; nt++) {
                *(__half2*)&g_ckj_n[rA * 32 + (nt - 4) * 8 + 2 * tq] =
                    __floats2half2_rn(c2[nt][0] * ia, c2[nt][1] * ia);
                *(__half2*)&g_ckj_n[rB * 32 + (nt - 4) * 8 + 2 * tq] =
                    __floats2half2_rn(c2[nt][2] * ib, c2[nt][3] * ib);
            }
            __syncwarp();
        }
    }
}

// ---------------- K3: triplets -> edge aggregation, 2 triplets per warp ------
__global__ void __launch_bounds__(256) k3_tri(const float* __restrict__ shb,
                                              const int* __restrict__ e_kj,
                                              const int* __restrict__ e_ji,
                                              const int* __restrict__ t_k) {
    int w = threadIdx.x >> 5, lane = threadIdx.x & 31;
    int t0 = (blockIdx.x * 8 + w) * 2;
    if (t0 >= NT) return;
    int t1 = t0 + 1;
    int kj0 = e_kj[t0], ji0 = e_ji[t0], kn0 = t_k[t0];
    int kj1 = e_kj[t1], ji1 = e_ji[t1], kn1 = t_k[t1];
    float acc0 = 0.f, acc1 = 0.f;
#pragma unroll
    for (int d = 0; d < NORB; d++) {
        float cf0 = __ldg(&g_rbw[kj0 * NORB + d]) * __ldg(&shb[t0 * NORB + d]);
        float cf1 = __ldg(&g_rbw[kj1 * NORB + d]) * __ldg(&shb[t1 * NORB + d]);
        float ck0 = __half2float(__ldg(&g_ckj_n[((size_t)kj0 * NORB + d) * CD + lane]));
        float ck1 = __half2float(__ldg(&g_ckj_n[((size_t)kj1 * NORB + d) * CD + lane]));
        acc0 = fmaf(cf0, ck0, acc0);
        acc1 = fmaf(cf1, ck1, acc1);
    }
    float s0 = acc0 * acc0, s1 = acc1 * acc1;
#pragma unroll
    for (int off = 16; off; off >>= 1) {
        s0 += __shfl_xor_sync(0xffffffffu, s0, off);
        s1 += __shfl_xor_sync(0xffffffffu, s1, off);
    }
    float tw0 = acc0 * (1.f / fmaxf(sqrtf(s0), 1e-12f)) * g_h[kn0 * 64 + 32 + lane];
    float tw1 = acc1 * (1.f / fmaxf(sqrtf(s1), 1e-12f)) * g_h[kn1 * 64 + 32 + lane];
    atomicAdd(&g_agg[(size_t)ji0 * CD + lane], tw0);
    atomicAdd(&g_agg[(size_t)ji1 * CD + lane], tw1);
}

// ---------------- K5b: MMA tbw + quad-shuffle lcao + scatter (16 edges/warp) -
__global__ void __launch_bounds__(256) k5b_edge(const float* __restrict__ W4,
                                                const float* __restrict__ b4,
                                                const int* __restrict__ idx_i) {
    __shared__ u32 sW4[32 * 36];       // tf32 [n][k] pad 36
    __shared__ float sb4[32];
    __shared__ u32 sA[8][16 * 36];     // per-warp silu(agg) tile, tf32
    int tid = threadIdx.x;
    for (int idx = tid; idx < 32 * 32; idx += 256) {
        int n = idx >> 5, k = idx & 31;
        sW4[n * 36 + k] = to_tf32(W4[idx]);
    }
    if (tid < 32) sb4[tid] = b4[tid];
    __syncthreads();

    int w = tid >> 5, lane = tid & 31;
    int gq = lane >> 2, tq = lane & 3;
    long e0 = (long)blockIdx.x * 128 + w * 16;
    if (e0 >= NE) return;
    u32* A = sA[w];

    // stage silu(agg) 16x32 tile as tf32
    for (int i = lane; i < 128; i += 32) {
        int rl = i >> 3, c4 = i & 7;
        long e = e0 + rl;
        uint4 v = make_uint4(0u, 0u, 0u, 0u);
        if (e < NE) {
            float4 f = *(const float4*)&g_agg[e * 32 + c4 * 4];
            v.x = to_tf32(silu(f.x)); v.y = to_tf32(silu(f.y));
            v.z = to_tf32(silu(f.z)); v.w = to_tf32(silu(f.w));
        }
        *(uint4*)&A[rl * 36 + c4 * 4] = v;
    }
    __syncwarp();

    // tbw MMA: (16x32) @ W4^T -> c1[nt][j]
    float c1[4][4];
#pragma unroll
    for (int nt = 0; nt < 4; nt++)
#pragma unroll
        for (int j = 0; j < 4; j++) c1[nt][j] = 0.f;
#pragma unroll
    for (int k0 = 0; k0 < 32; k0 += 8) {
        u32 a0 = A[gq * 36 + k0 + tq];
        u32 a1 = A[(gq + 8) * 36 + k0 + tq];
        u32 a2 = A[gq * 36 + k0 + tq + 4];
        u32 a3 = A[(gq + 8) * 36 + k0 + tq + 4];
#pragma unroll
        for (int nt = 0; nt < 4; nt++) {
            u32 b0 = sW4[(nt * 8 + gq) * 36 + k0 + tq];
            u32 b1 = sW4[(nt * 8 + gq) * 36 + k0 + tq + 4];
            mma_tf32(c1[nt][0], c1[nt][1], c1[nt][2], c1[nt][3], a0, a1, a2, a3, b0, b1);
        }
    }

    // process rows sequentially: half = 0 -> row e0+gq (c1[][0..1]), half = 1 -> e0+gq+8
#pragma unroll
    for (int half = 0; half < 2; half++) {
        long row = e0 + gq + half * 8;
        if (row >= NE) continue;
        // tb per owned channel (8 per lane): col = nt*8 + 2tq (+1)
        float tb[8];
#pragma unroll
        for (int nt = 0; nt < 4; nt++) {
            int col = nt * 8 + 2 * tq;
            tb[nt * 2]     = 1.f + sb4[col]     + c1[nt][half * 2];
            tb[nt * 2 + 1] = 1.f + sb4[col + 1] + c1[nt][half * 2 + 1];
        }
        size_t base = (size_t)row * (NORB * CD);
        // pass 1: per-orbital squared sums over this lane's 8 channels
        float ss[NORB];
#pragma unroll
        for (int d = 0; d < NORB; d++) {
            float p = 0.f;
#pragma unroll
            for (int nt = 0; nt < 4; nt++) {
                __half2 h = __ldg((const __half2*)&g_cji_c[base + d * 32 + nt * 8 + 2 * tq]);
                float2 f = __half22float2(h);
                float x0 = f.x * tb[nt * 2], x1 = f.y * tb[nt * 2 + 1];
                p = fmaf(x0, x0, fmaf(x1, x1, p));
            }
            ss[d] = p;
        }
        // quad reduce (channels of one row live in a 4-lane quad)
#pragma unroll
        for (int off = 1; off <= 2; off <<= 1) {
#pragma unroll
            for (int d = 0; d < NORB; d++)
                ss[d] += __shfl_xor_sync(0xffffffffu, ss[d], off);
        }
        float rwinv[NORB];
#pragma unroll
        for (int d = 0; d < NORB; d++)
            rwinv[d] = __ldg(&g_rbw[row * NORB + d]) / fmaxf(sqrtf(ss[d]), 1e-12f);
        // pass 2: lc per channel (L1-hot reload)
        float lc[8];
#pragma unroll
        for (int j = 0; j < 8; j++) lc[j] = 0.f;
#pragma unroll
        for (int d = 0; d < NORB; d++) {
#pragma unroll
            for (int nt = 0; nt < 4; nt++) {
                __half2 h = __ldg((const __half2*)&g_cji_c[base + d * 32 + nt * 8 + 2 * tq]);
                float2 f = __half22float2(h);
                lc[nt * 2]     = fmaf(rwinv[d], f.x, lc[nt * 2]);
                lc[nt * 2 + 1] = fmaf(rwinv[d], f.y, lc[nt * 2 + 1]);
            }
        }
        float s = 0.f;
#pragma unroll
        for (int j = 0; j < 8; j++) {
            lc[j] *= tb[j];
            s = fmaf(lc[j], lc[j], s);
        }
        s += __shfl_xor_sync(0xffffffffu, s, 1);
        s += __shfl_xor_sync(0xffffffffu, s, 2);
        float inv = 1.f / fmaxf(sqrtf(s), 1e-12f);
        int ni = __ldg(&idx_i[row]);
#pragma unroll
        for (int nt = 0; nt < 4; nt++) {
            int col = nt * 8 + 2 * tq;
            float2 nf2 = *(const float2*)&g_nf[row * 32 + col];
            atomicAdd(&g_acc[ni * CD + col],     lc[nt * 2] * inv * nf2.x);
            atomicAdd(&g_acc[ni * CD + col + 1], lc[nt * 2 + 1] * inv * nf2.y);
        }
    }
}

// ---------------- K6: out = x + acc @ W7^T ----------------------------------
__global__ void __launch_bounds__(256) k6_out(const float* __restrict__ x,
                                              const float* __restrict__ W7,
                                              float* __restrict__ out) {
    __shared__ float sW[32 * 128];
    __shared__ float sa[2][32];
    int tid = threadIdx.x;
    for (int idx = tid; idx < 128 * 32; idx += 256) {
        int hc = idx / 32, c = idx % 32;
        sW[c * 128 + hc] = W7[idx];
    }
    int n0 = blockIdx.x * 2;
    if (tid < 64) {
        int r = tid >> 5, c = tid & 31;
        int n = n0 + r;
        if (n < NN) sa[r][c] = g_acc[n * 32 + c];
    }
    __syncthreads();
    int r = tid >> 7, hc = tid & 127;
    int n = n0 + r;
    if (n >= NN) return;
    float acc = x[n * 128 + hc];
#pragma unroll
    for (int c = 0; c < 32; c++) acc = fmaf(sa[r][c], sW[c * 128 + hc], acc);
    out[n * 128 + hc] = acc;
}

// ---------------- host launcher ---------------------------------------------
extern "C" void kernel_launch(void* const* d_in, const int* in_sizes, int n_in,
                              void* d_out, int out_size) {
    int o_ii, o_ij, o_tk, o_ekj, o_eji;
    int o_W1, o_b1, o_W2, o_W3, o_W4, o_b4, o_W5, o_b5, o_W6, o_b6, o_W7;
    if (in_sizes[5] == NE) { // dict order: idx_i at slot 5
        o_ii = 5; o_ij = 6; o_tk = 7; o_ekj = 8; o_eji = 9;
        o_W1 = 10; o_b1 = 11; o_W2 = 12; o_W3 = 13; o_W4 = 14; o_b4 = 15;
        o_W5 = 16; o_b5 = 17; o_W6 = 18; o_b6 = 19; o_W7 = 20;
    } else {                 // signature order: W1 at slot 5
        o_W1 = 5; o_b1 = 6; o_W2 = 7; o_W3 = 8; o_W4 = 9; o_b4 = 10;
        o_W5 = 11; o_b5 = 12; o_W6 = 13; o_b6 = 14; o_W7 = 15;
        o_ii = 16; o_ij = 17; o_tk = 18; o_ekj = 19; o_eji = 20;
    }
    const float* x   = (const float*)d_in[0];
    const float* cji = (const float*)d_in[1];
    const float* cw  = (const float*)d_in[2];
    const float* rb  = (const float*)d_in[3];
    const float* shb = (const float*)d_in[4];
    const int* ii  = (const int*)d_in[o_ii];
    const int* ij  = (const int*)d_in[o_ij];
    const int* tk  = (const int*)d_in[o_tk];
    const int* ekj = (const int*)d_in[o_ekj];
    const int* eji = (const int*)d_in[o_eji];
    const float* W1 = (const float*)d_in[o_W1];
    const float* b1 = (const float*)d_in[o_b1];
    const float* W2 = (const float*)d_in[o_W2];
    const float* W3 = (const float*)d_in[o_W3];
    const float* W4 = (const float*)d_in[o_W4];
    const float* b4 = (const float*)d_in[o_b4];
    const float* W5 = (const float*)d_in[o_W5];
    const float* b5 = (const float*)d_in[o_b5];
    const float* W6 = (const float*)d_in[o_W6];
    const float* b6 = (const float*)d_in[o_b6];
    const float* W7 = (const float*)d_in[o_W7];
    float* out = (float*)d_out;

    // 5 launches; slot 4 (ncu window) = new k5b for verification.
    k01<<<K1_BLOCKS + K0_BLOCKS, 256>>>(rb, cw, x, W1, b1);
    k5a_k2<<<K5A_BLOCKS + K2_BLOCKS, 256>>>(cji, W2, W3, W5, b5, W6, b6, ii, ij);
    k3_tri<<<(NT + 15) / 16, 256>>>(shb, ekj, eji, tk);
    k5b_edge<<<K5A_BLOCKS, 256>>>(W4, b4, ii);
    k6_out<<<(NN + 1) / 2, 256>>>(x, W7, out);
}

// round 17
// speedup vs baseline: 1.3249x; 1.0199x over previous
#include <cuda_runtime.h>
#include <cuda_fp16.h>
#include <math.h>

#define NN 10000
#define NE 200000
#define NT 400000
#define NORB 9
#define HD 128
#define CFD 64
#define CD 32
#define R_TOT (NE * NORB)   // 1,800,000 flattened (edge,orb) rows
#define K2_BLOCKS 592       // 148 SMs x 4 resident CTAs
#define K5A_BLOCKS 1563     // ceil(NE/128)
#define K1_BLOCKS 2500      // ceil(NN/4)
#define K0_BLOCKS 25000     // ceil(NE*CD/256)

typedef unsigned long long u64;
typedef unsigned int u32;

// ---------------- scratch (device globals; no allocation allowed) ----------
__device__ float g_h[NN * 64];                     // [0:32)=silu(xh), [32:64)=sigm(xk)
__device__ __half g_cji_c[(size_t)NE * NORB * CD]; // 115.2 MB (fp16)
__device__ __half g_ckj_n[(size_t)NE * NORB * CD]; // 115.2 MB (fp16, pre-normalized)
__device__ float g_rbw[NE * NORB];
__device__ float g_agg[(size_t)NE * CD];
__device__ float g_nf[(size_t)NE * CD];            // node-feature MLP output
__device__ float g_acc[NN * CD];

// ---- activations (proven __expf path) ---------------------------------------
__device__ __forceinline__ float sigm(float x) { return 1.f / (1.f + __expf(-x)); }
__device__ __forceinline__ float silu(float x) { return x * sigm(x); }

__device__ __forceinline__ float warp_sum(float s) {
#pragma unroll
    for (int off = 16; off; off >>= 1) s += __shfl_xor_sync(0xffffffffu, s, off);
    return s;
}

// ---- tf32 helpers ------------------------------------------------------------
__device__ __forceinline__ u32 to_tf32(float f) {
    u32 r; asm("cvt.rna.tf32.f32 %0,%1;" : "=r"(r) : "f"(f)); return r;
}
__device__ __forceinline__ void mma_tf32(float& c0, float& c1, float& c2, float& c3,
                                         u32 a0, u32 a1, u32 a2, u32 a3,
                                         u32 b0, u32 b1) {
    asm("mma.sync.aligned.m16n8k8.row.col.f32.tf32.tf32.f32 "
        "{%0,%1,%2,%3},{%4,%5,%6,%7},{%8,%9},{%0,%1,%2,%3};"
        : "+f"(c0), "+f"(c1), "+f"(c2), "+f"(c3)
        : "r"(a0), "r"(a1), "r"(a2), "r"(a3), "r"(b0), "r"(b1));
}

// ---- fp16 m16n8k16 MMA (k2) -------------------------------------------------
__device__ __forceinline__ void mma_f16(float& c0, float& c1, float& c2, float& c3,
                                        u32 a0, u32 a1, u32 a2, u32 a3,
                                        u32 b0, u32 b1) {
    asm("mma.sync.aligned.m16n8k16.row.col.f32.f16.f16.f32 "
        "{%0,%1,%2,%3},{%4,%5,%6,%7},{%8,%9},{%0,%1,%2,%3};"
        : "+f"(c0), "+f"(c1), "+f"(c2), "+f"(c3)
        : "r"(a0), "r"(a1), "r"(a2), "r"(a3), "r"(b0), "r"(b1));
}
__device__ __forceinline__ u32 h2u(float x, float y) {
    __half2 h = __floats2half2_rn(x, y);
    return *(u32*)&h;
}

// ---------------- K01: fused init (k0) + node MLP (k1) -----------------------
__global__ void __launch_bounds__(256) k01(const float* __restrict__ rb,
                                           const float* __restrict__ cw,
                                           const float* __restrict__ x,
                                           const float* __restrict__ W1,
                                           const float* __restrict__ b1) {
    __shared__ float sW[HD * 64];
    __shared__ float sx[4][HD];
    int tid = threadIdx.x;
    if (blockIdx.x < K1_BLOCKS) {
        for (int idx = tid; idx < 64 * HD; idx += 256) {
            int o = idx / HD, k = idx % HD;
            sW[k * 64 + o] = W1[idx];
        }
        int n0 = blockIdx.x * 4;
#pragma unroll
        for (int r = 0; r < 4; r++) {
            int n = n0 + r;
            if (n < NN)
                for (int k = tid; k < HD; k += 256) sx[r][k] = x[n * HD + k];
        }
        __syncthreads();
        int r = tid / 64, o = tid % 64;
        int n = n0 + r;
        if (n >= NN) return;
        float acc = b1[o];
#pragma unroll 8
        for (int k = 0; k < HD; k++) acc = fmaf(sx[r][k], sW[k * 64 + o], acc);
        g_h[n * 64 + o] = (o < 32) ? silu(acc) : sigm(acc);
    } else {
        int i = (blockIdx.x - K1_BLOCKS) * 256 + tid;
        if (i < NE * CD) g_agg[i] = 0.f;
        if (i < NN * CD) g_acc[i] = 0.f;
        if (i < NE * NORB) g_rbw[i] = rb[i] * cw[i / NORB];
    }
}

// ---------------- fused K5A (blocks [0,1563)) + K2 (blocks [1563,2155)) ------
__global__ void __launch_bounds__(256, 4) k5a_k2(const float* __restrict__ cji,
                                                 const float* __restrict__ W2,
                                                 const float* __restrict__ W3,
                                                 const float* __restrict__ W5,
                                                 const float* __restrict__ b5,
                                                 const float* __restrict__ W6,
                                                 const float* __restrict__ b6,
                                                 const int* __restrict__ idx_i,
                                                 const int* __restrict__ idx_j) {
    __shared__ __align__(16) char smem[48384];
    int tid = threadIdx.x;
    int w = tid >> 5, lane = tid & 31;
    int gq = lane >> 2, tq = lane & 3;

    if (blockIdx.x < K5A_BLOCKS) {
        // ================= k5a body (tf32) =================
        u32* sW5 = (u32*)smem;
        u32* sW6 = (u32*)(smem + 8704);
        float* sb5 = (float*)(smem + 13312);
        float* sb6 = (float*)(smem + 13440);
        u32* sA1w = (u32*)(smem + 13568);
        for (int idx = tid; idx < 32 * 64; idx += 256) {
            int n = idx >> 6, k = idx & 63;
            sW5[n * 68 + k] = to_tf32(W5[idx]);
        }
        for (int idx = tid; idx < 32 * 32; idx += 256) {
            int n = idx >> 5, k = idx & 31;
            sW6[n * 36 + k] = to_tf32(W6[idx]);
        }
        if (tid < 32) { sb5[tid] = b5[tid]; sb6[tid] = b6[tid]; }
        __syncthreads();

        long row0 = (long)blockIdx.x * 128 + w * 16;
        u32* A1 = sA1w + w * (16 * 68);
        u32* A2 = A1;

        for (int i = lane; i < 256; i += 32) {
            int rl = i >> 4, c4 = i & 15;
            long e = row0 + rl;
            uint4 v = make_uint4(0u, 0u, 0u, 0u);
            if (e < NE) {
                int n = (c4 < 8) ? __ldg(&idx_i[e]) : __ldg(&idx_j[e]);
                float4 f = *(const float4*)&g_h[n * 64 + (c4 & 7) * 4];
                v.x = to_tf32(f.x); v.y = to_tf32(f.y);
                v.z = to_tf32(f.z); v.w = to_tf32(f.w);
            }
            *(uint4*)&A1[rl * 68 + c4 * 4] = v;
        }
        __syncwarp();

        float c1[4][4];
#pragma unroll
        for (int nt = 0; nt < 4; nt++)
#pragma unroll
            for (int j = 0; j < 4; j++) c1[nt][j] = 0.f;
#pragma unroll
        for (int k0 = 0; k0 < 64; k0 += 8) {
            u32 a0 = A1[gq * 68 + k0 + tq];
            u32 a1 = A1[(gq + 8) * 68 + k0 + tq];
            u32 a2 = A1[gq * 68 + k0 + tq + 4];
            u32 a3 = A1[(gq + 8) * 68 + k0 + tq + 4];
#pragma unroll
            for (int nt = 0; nt < 4; nt++) {
                u32 b0 = sW5[(nt * 8 + gq) * 68 + k0 + tq];
                u32 b1 = sW5[(nt * 8 + gq) * 68 + k0 + tq + 4];
                mma_tf32(c1[nt][0], c1[nt][1], c1[nt][2], c1[nt][3], a0, a1, a2, a3, b0, b1);
            }
        }
        __syncwarp();
#pragma unroll
        for (int nt = 0; nt < 4; nt++) {
            int col = nt * 8 + 2 * tq;
            A2[gq * 36 + col]           = to_tf32(silu(c1[nt][0] + sb5[col]));
            A2[gq * 36 + col + 1]       = to_tf32(silu(c1[nt][1] + sb5[col + 1]));
            A2[(gq + 8) * 36 + col]     = to_tf32(silu(c1[nt][2] + sb5[col]));
            A2[(gq + 8) * 36 + col + 1] = to_tf32(silu(c1[nt][3] + sb5[col + 1]));
        }
        __syncwarp();

        float c2[4][4];
#pragma unroll
        for (int nt = 0; nt < 4; nt++)
#pragma unroll
            for (int j = 0; j < 4; j++) c2[nt][j] = 0.f;
#pragma unroll
        for (int k0 = 0; k0 < 32; k0 += 8) {
            u32 a0 = A2[gq * 36 + k0 + tq];
            u32 a1 = A2[(gq + 8) * 36 + k0 + tq];
            u32 a2 = A2[gq * 36 + k0 + tq + 4];
            u32 a3 = A2[(gq + 8) * 36 + k0 + tq + 4];
#pragma unroll
            for (int nt = 0; nt < 4; nt++) {
                u32 b0 = sW6[(nt * 8 + gq) * 36 + k0 + tq];
                u32 b1 = sW6[(nt * 8 + gq) * 36 + k0 + tq + 4];
                mma_tf32(c2[nt][0], c2[nt][1], c2[nt][2], c2[nt][3], a0, a1, a2, a3, b0, b1);
            }
        }
        long rA = row0 + gq, rB = row0 + gq + 8;
        if (rA < NE) {
#pragma unroll
            for (int nt = 0; nt < 4; nt++) {
                int col = nt * 8 + 2 * tq;
                *(float2*)&g_nf[rA * 32 + col] =
                    make_float2(c2[nt][0] + sb6[col], c2[nt][1] + sb6[col + 1]);
            }
        }
        if (rB < NE) {
#pragma unroll
            for (int nt = 0; nt < 4; nt++) {
                int col = nt * 8 + 2 * tq;
                *(float2*)&g_nf[rB * 32 + col] =
                    make_float2(c2[nt][2] + sb6[col], c2[nt][3] + sb6[col + 1]);
            }
        }
    } else {
        // ================= k2 body (fp16, persistent) =================
        __half* sW2h = (__half*)smem;
        __half* sW3h = (__half*)(smem + 4608);
        __half* sA1h = (__half*)(smem + 9728);
        for (int idx = tid; idx < 32 * 64; idx += 256) {
            int n = idx >> 6, k = idx & 63;
            sW2h[n * 72 + k] = __float2half(W2[idx]);
        }
        for (int idx = tid; idx < 64 * 32; idx += 256) {
            int n = idx >> 5, k = idx & 31;
            sW3h[n * 40 + k] = __float2half(W3[idx]);
        }
        __syncthreads();

        u32* A1 = (u32*)(sA1h + w * (16 * 72));
        u32* A2 = A1;
        const u32* W2w = (const u32*)sW2h;
        const u32* W3w = (const u32*)sW3h;

        const int n_tiles = R_TOT / 16;
        const int gw0 = (blockIdx.x - K5A_BLOCKS) * 8 + w;
        const int gw_stride = K2_BLOCKS * 8;

        for (int tile = gw0; tile < n_tiles; tile += gw_stride) {
            long row0 = (long)tile * 16;
            for (int i = lane; i < 256; i += 32) {
                int rl = i >> 4, c4 = i & 15;
                float4 f = *(const float4*)(cji + (row0 + rl) * 64 + c4 * 4);
                int wd = rl * 36 + c4 * 2;
                A1[wd]     = h2u(silu(f.x), silu(f.y));
                A1[wd + 1] = h2u(silu(f.z), silu(f.w));
            }
            __syncwarp();

            float c1[4][4];
#pragma unroll
            for (int nt = 0; nt < 4; nt++)
#pragma unroll
                for (int j = 0; j < 4; j++) c1[nt][j] = 0.f;
#pragma unroll
            for (int ks = 0; ks < 4; ks++) {
                int kw = ks * 8;
                u32 a0 = A1[gq * 36 + kw + tq];
                u32 a1 = A1[(gq + 8) * 36 + kw + tq];
                u32 a2 = A1[gq * 36 + kw + tq + 4];
                u32 a3 = A1[(gq + 8) * 36 + kw + tq + 4];
#pragma unroll
                for (int nt = 0; nt < 4; nt++) {
                    u32 b0 = W2w[(nt * 8 + gq) * 36 + kw + tq];
                    u32 b1 = W2w[(nt * 8 + gq) * 36 + kw + tq + 4];
                    mma_f16(c1[nt][0], c1[nt][1], c1[nt][2], c1[nt][3], a0, a1, a2, a3, b0, b1);
                }
            }
            __syncwarp();
#pragma unroll
            for (int nt = 0; nt < 4; nt++) {
                A2[gq * 20 + nt * 4 + tq]       = h2u(silu(c1[nt][0]), silu(c1[nt][1]));
                A2[(gq + 8) * 20 + nt * 4 + tq] = h2u(silu(c1[nt][2]), silu(c1[nt][3]));
            }
            __syncwarp();

            float c2[8][4];
#pragma unroll
            for (int nt = 0; nt < 8; nt++)
#pragma unroll
                for (int j = 0; j < 4; j++) c2[nt][j] = 0.f;
#pragma unroll
            for (int ks = 0; ks < 2; ks++) {
                int kw = ks * 8;
                u32 a0 = A2[gq * 20 + kw + tq];
                u32 a1 = A2[(gq + 8) * 20 + kw + tq];
                u32 a2 = A2[gq * 20 + kw + tq + 4];
                u32 a3 = A2[(gq + 8) * 20 + kw + tq + 4];
#pragma unroll
                for (int nt = 0; nt < 8; nt++) {
                    u32 b0 = W3w[(nt * 8 + gq) * 20 + kw + tq];
                    u32 b1 = W3w[(nt * 8 + gq) * 20 + kw + tq + 4];
                    mma_f16(c2[nt][0], c2[nt][1], c2[nt][2], c2[nt][3], a0, a1, a2, a3, b0, b1);
                }
            }

            long rA = row0 + gq, rB = row0 + gq + 8;
#pragma unroll
            for (int nt = 0; nt < 4; nt++) {
                *(__half2*)&g_cji_c[rA * 32 + nt * 8 + 2 * tq] = __floats2half2_rn(c2[nt][0], c2[nt][1]);
                *(__half2*)&g_cji_c[rB * 32 + nt * 8 + 2 * tq] = __floats2half2_rn(c2[nt][2], c2[nt][3]);
            }
            float sa = 0.f, sb = 0.f;
#pragma unroll
            for (int nt = 4; nt < 8; nt++) {
                sa = fmaf(c2[nt][0], c2[nt][0], fmaf(c2[nt][1], c2[nt][1], sa));
                sb = fmaf(c2[nt][2], c2[nt][2], fmaf(c2[nt][3], c2[nt][3], sb));
            }
            sa += __shfl_xor_sync(0xffffffffu, sa, 1);
            sa += __shfl_xor_sync(0xffffffffu, sa, 2);
            sb += __shfl_xor_sync(0xffffffffu, sb, 1);
            sb += __shfl_xor_sync(0xffffffffu, sb, 2);
            float ia = 1.f / fmaxf(sqrtf(sa), 1e-12f);
            float ib = 1.f / fmaxf(sqrtf(sb), 1e-12f);
#pragma unroll
            for (int nt = 4; nt < 8; nt++) {
                *(__half2*)&g_ckj_n[rA * 32 + (nt - 4) * 8 + 2 * tq] =
                    __floats2half2_rn(c2[nt][0] * ia, c2[nt][1] * ia);
                *(__half2*)&g_ckj_n[rB * 32 + (nt - 4) * 8 + 2 * tq] =
                    __floats2half2_rn(c2[nt][2] * ib, c2[nt][3] * ib);
            }
            __syncwarp();
        }
    }
}

// ---------------- K3: triplets -> edge aggregation, 2 triplets per warp ------
__global__ void __launch_bounds__(256) k3_tri(const float* __restrict__ shb,
                                              const int* __restrict__ e_kj,
                                              const int* __restrict__ e_ji,
                                              const int* __restrict__ t_k) {
    int w = threadIdx.x >> 5, lane = threadIdx.x & 31;
    int t0 = (blockIdx.x * 8 + w) * 2;
    if (t0 >= NT) return;
    int t1 = t0 + 1;
    int kj0 = e_kj[t0], ji0 = e_ji[t0], kn0 = t_k[t0];
    int kj1 = e_kj[t1], ji1 = e_ji[t1], kn1 = t_k[t1];
    float acc0 = 0.f, acc1 = 0.f;
#pragma unroll
    for (int d = 0; d < NORB; d++) {
        float cf0 = __ldg(&g_rbw[kj0 * NORB + d]) * __ldg(&shb[t0 * NORB + d]);
        float cf1 = __ldg(&g_rbw[kj1 * NORB + d]) * __ldg(&shb[t1 * NORB + d]);
        float ck0 = __half2float(__ldg(&g_ckj_n[((size_t)kj0 * NORB + d) * CD + lane]));
        float ck1 = __half2float(__ldg(&g_ckj_n[((size_t)kj1 * NORB + d) * CD + lane]));
        acc0 = fmaf(cf0, ck0, acc0);
        acc1 = fmaf(cf1, ck1, acc1);
    }
    float s0 = acc0 * acc0, s1 = acc1 * acc1;
#pragma unroll
    for (int off = 16; off; off >>= 1) {
        s0 += __shfl_xor_sync(0xffffffffu, s0, off);
        s1 += __shfl_xor_sync(0xffffffffu, s1, off);
    }
    float tw0 = acc0 * (1.f / fmaxf(sqrtf(s0), 1e-12f)) * g_h[kn0 * 64 + 32 + lane];
    float tw1 = acc1 * (1.f / fmaxf(sqrtf(s1), 1e-12f)) * g_h[kn1 * 64 + 32 + lane];
    atomicAdd(&g_agg[(size_t)ji0 * CD + lane], tw0);
    atomicAdd(&g_agg[(size_t)ji1 * CD + lane], tw1);
}

// ---------------- K5b: MMA tbw + quad-shuffle lcao, low-reg (tb via SMEM) ----
__global__ void __launch_bounds__(256, 4) k5b_edge(const float* __restrict__ W4,
                                                   const float* __restrict__ b4,
                                                   const int* __restrict__ idx_i) {
    __shared__ u32 sW4[32 * 36];       // tf32 [n][k] pad 36
    __shared__ float sb4[32];
    __shared__ u32 sA[8][16 * 36];     // staging tile; later reused as tb tile
    int tid = threadIdx.x;
    for (int idx = tid; idx < 32 * 32; idx += 256) {
        int n = idx >> 5, k = idx & 31;
        sW4[n * 36 + k] = to_tf32(W4[idx]);
    }
    if (tid < 32) sb4[tid] = b4[tid];
    __syncthreads();

    int w = tid >> 5, lane = tid & 31;
    int gq = lane >> 2, tq = lane & 3;
    long e0 = (long)blockIdx.x * 128 + w * 16;
    if (e0 >= NE) return;
    u32* A = sA[w];

    // stage silu(agg) 16x32 tile as tf32
    for (int i = lane; i < 128; i += 32) {
        int rl = i >> 3, c4 = i & 7;
        long e = e0 + rl;
        uint4 v = make_uint4(0u, 0u, 0u, 0u);
        if (e < NE) {
            float4 f = *(const float4*)&g_agg[e * 32 + c4 * 4];
            v.x = to_tf32(silu(f.x)); v.y = to_tf32(silu(f.y));
            v.z = to_tf32(silu(f.z)); v.w = to_tf32(silu(f.w));
        }
        *(uint4*)&A[rl * 36 + c4 * 4] = v;
    }
    __syncwarp();

    // tbw MMA: (16x32) @ W4^T -> c1
    {
        float c1[4][4];
#pragma unroll
        for (int nt = 0; nt < 4; nt++)
#pragma unroll
            for (int j = 0; j < 4; j++) c1[nt][j] = 0.f;
#pragma unroll
        for (int k0 = 0; k0 < 32; k0 += 8) {
            u32 a0 = A[gq * 36 + k0 + tq];
            u32 a1 = A[(gq + 8) * 36 + k0 + tq];
            u32 a2 = A[gq * 36 + k0 + tq + 4];
            u32 a3 = A[(gq + 8) * 36 + k0 + tq + 4];
#pragma unroll
            for (int nt = 0; nt < 4; nt++) {
                u32 b0 = sW4[(nt * 8 + gq) * 36 + k0 + tq];
                u32 b1 = sW4[(nt * 8 + gq) * 36 + k0 + tq + 4];
                mma_tf32(c1[nt][0], c1[nt][1], c1[nt][2], c1[nt][3], a0, a1, a2, a3, b0, b1);
            }
        }
        // A tile fully consumed -> overwrite with tb tile (c1 dies here)
        __syncwarp();
        float* sTB = (float*)A;   // [row][col], stride 36 words
#pragma unroll
        for (int nt = 0; nt < 4; nt++) {
            int col = nt * 8 + 2 * tq;
            sTB[gq * 36 + col]           = 1.f + sb4[col]     + c1[nt][0];
            sTB[gq * 36 + col + 1]       = 1.f + sb4[col + 1] + c1[nt][1];
            sTB[(gq + 8) * 36 + col]     = 1.f + sb4[col]     + c1[nt][2];
            sTB[(gq + 8) * 36 + col + 1] = 1.f + sb4[col + 1] + c1[nt][3];
        }
    }
    __syncwarp();
    const float* sTB = (const float*)A;

    // process 2 rows per lane sequentially; tb reloaded from SMEM (low regs)
#pragma unroll 1
    for (int half = 0; half < 2; half++) {
        int rl = gq + half * 8;
        long row = e0 + rl;
        if (row >= NE) continue;
        float tb[8];
#pragma unroll
        for (int nt = 0; nt < 4; nt++) {
            int col = nt * 8 + 2 * tq;
            tb[nt * 2]     = sTB[rl * 36 + col];
            tb[nt * 2 + 1] = sTB[rl * 36 + col + 1];
        }
        size_t base = (size_t)row * (NORB * CD);
        // pass 1: per-orbital squared sums over this lane's 8 channels
        float ss[NORB];
#pragma unroll
        for (int d = 0; d < NORB; d++) {
            float p = 0.f;
#pragma unroll
            for (int nt = 0; nt < 4; nt++) {
                __half2 h = __ldg((const __half2*)&g_cji_c[base + d * 32 + nt * 8 + 2 * tq]);
                float2 f = __half22float2(h);
                float x0 = f.x * tb[nt * 2], x1 = f.y * tb[nt * 2 + 1];
                p = fmaf(x0, x0, fmaf(x1, x1, p));
            }
            ss[d] = p;
        }
#pragma unroll
        for (int off = 1; off <= 2; off <<= 1) {
#pragma unroll
            for (int d = 0; d < NORB; d++)
                ss[d] += __shfl_xor_sync(0xffffffffu, ss[d], off);
        }
        // reuse ss[] in place as rbw/||.||
#pragma unroll
        for (int d = 0; d < NORB; d++)
            ss[d] = __ldg(&g_rbw[row * NORB + d]) / fmaxf(sqrtf(ss[d]), 1e-12f);
        // pass 2: lc per channel (L1-hot reload)
        float lc[8];
#pragma unroll
        for (int j = 0; j < 8; j++) lc[j] = 0.f;
#pragma unroll
        for (int d = 0; d < NORB; d++) {
#pragma unroll
            for (int nt = 0; nt < 4; nt++) {
                __half2 h = __ldg((const __half2*)&g_cji_c[base + d * 32 + nt * 8 + 2 * tq]);
                float2 f = __half22float2(h);
                lc[nt * 2]     = fmaf(ss[d], f.x, lc[nt * 2]);
                lc[nt * 2 + 1] = fmaf(ss[d], f.y, lc[nt * 2 + 1]);
            }
        }
        float s = 0.f;
#pragma unroll
        for (int j = 0; j < 8; j++) {
            lc[j] *= tb[j];
            s = fmaf(lc[j], lc[j], s);
        }
        s += __shfl_xor_sync(0xffffffffu, s, 1);
        s += __shfl_xor_sync(0xffffffffu, s, 2);
        float inv = 1.f / fmaxf(sqrtf(s), 1e-12f);
        int ni = __ldg(&idx_i[row]);
#pragma unroll
        for (int nt = 0; nt < 4; nt++) {
            int col = nt * 8 + 2 * tq;
            float2 nf2 = *(const float2*)&g_nf[row * 32 + col];
            atomicAdd(&g_acc[ni * CD + col],     lc[nt * 2] * inv * nf2.x);
            atomicAdd(&g_acc[ni * CD + col + 1], lc[nt * 2 + 1] * inv * nf2.y);
        }
    }
}

// ---------------- K6: out = x + acc @ W7^T ----------------------------------
__global__ void __launch_bounds__(256) k6_out(const float* __restrict__ x,
                                              const float* __restrict__ W7,
                                              float* __restrict__ out) {
    __shared__ float sW[32 * 128];
    __shared__ float sa[2][32];
    int tid = threadIdx.x;
    for (int idx = tid; idx < 128 * 32; idx += 256) {
        int hc = idx / 32, c = idx % 32;
        sW[c * 128 + hc] = W7[idx];
    }
    int n0 = blockIdx.x * 2;
    if (tid < 64) {
        int r = tid >> 5, c = tid & 31;
        int n = n0 + r;
        if (n < NN) sa[r][c] = g_acc[n * 32 + c];
    }
    __syncthreads();
    int r = tid >> 7, hc = tid & 127;
    int n = n0 + r;
    if (n >= NN) return;
    float acc = x[n * 128 + hc];
#pragma unroll
    for (int c = 0; c < 32; c++) acc = fmaf(sa[r][c], sW[c * 128 + hc], acc);
    out[n * 128 + hc] = acc;
}

// ---------------- host launcher ---------------------------------------------
extern "C" void kernel_launch(void* const* d_in, const int* in_sizes, int n_in,
                              void* d_out, int out_size) {
    int o_ii, o_ij, o_tk, o_ekj, o_eji;
    int o_W1, o_b1, o_W2, o_W3, o_W4, o_b4, o_W5, o_b5, o_W6, o_b6, o_W7;
    if (in_sizes[5] == NE) { // dict order: idx_i at slot 5
        o_ii = 5; o_ij = 6; o_tk = 7; o_ekj = 8; o_eji = 9;
        o_W1 = 10; o_b1 = 11; o_W2 = 12; o_W3 = 13; o_W4 = 14; o_b4 = 15;
        o_W5 = 16; o_b5 = 17; o_W6 = 18; o_b6 = 19; o_W7 = 20;
    } else {                 // signature order: W1 at slot 5
        o_W1 = 5; o_b1 = 6; o_W2 = 7; o_W3 = 8; o_W4 = 9; o_b4 = 10;
        o_W5 = 11; o_b5 = 12; o_W6 = 13; o_b6 = 14; o_W7 = 15;
        o_ii = 16; o_ij = 17; o_tk = 18; o_ekj = 19; o_eji = 20;
    }
    const float* x   = (const float*)d_in[0];
    const float* cji = (const float*)d_in[1];
    const float* cw  = (const float*)d_in[2];
    const float* rb  = (const float*)d_in[3];
    const float* shb = (const float*)d_in[4];
    const int* ii  = (const int*)d_in[o_ii];
    const int* ij  = (const int*)d_in[o_ij];
    const int* tk  = (const int*)d_in[o_tk];
    const int* ekj = (const int*)d_in[o_ekj];
    const int* eji = (const int*)d_in[o_eji];
    const float* W1 = (const float*)d_in[o_W1];
    const float* b1 = (const float*)d_in[o_b1];
    const float* W2 = (const float*)d_in[o_W2];
    const float* W3 = (const float*)d_in[o_W3];
    const float* W4 = (const float*)d_in[o_W4];
    const float* b4 = (const float*)d_in[o_b4];
    const float* W5 = (const float*)d_in[o_W5];
    const float* b5 = (const float*)d_in[o_b5];
    const float* W6 = (const float*)d_in[o_W6];
    const float* b6 = (const float*)d_in[o_b6];
    const float* W7 = (const float*)d_in[o_W7];
    float* out = (float*)d_out;

    // 5 launches; slot 4 (ncu window) = k5b for verification.
    k01<<<K1_BLOCKS + K0_BLOCKS, 256>>>(rb, cw, x, W1, b1);
    k5a_k2<<<K5A_BLOCKS + K2_BLOCKS, 256>>>(cji, W2, W3, W5, b5, W6, b6, ii, ij);
    k3_tri<<<(NT + 15) / 16, 256>>>(shb, ekj, eji, tk);
    k5b_edge<<<K5A_BLOCKS, 256>>>(W4, b4, ii);
    k6_out<<<(NN + 1) / 2, 256>>>(x, W7, out);
}